// round 12
// baseline (speedup 1.0000x reference)
#include <cuda_runtime.h>
#include <cuda_bf16.h>
#include <cstdint>
#include <cstddef>

#define BATCH 8
#define CDIM 256
#define CIDIM 128
#define NPIX 4096
#define QT 128
#define JT 64
#define NJT (NPIX / JT)
#define L2E 1.4426950408889634f

// ---------------- scratch (__device__ globals; no allocation) ----------------
static __device__ __nv_bfloat16 g_x_h [BATCH * CDIM * NPIX];   // x split  [B][C][N]
static __device__ __nv_bfloat16 g_x_l [BATCH * CDIM * NPIX];
static __device__ __nv_bfloat16 g_wsp_h[4 * 32768];            // th,ph,g,W_w split
static __device__ __nv_bfloat16 g_wsp_l[4 * 32768];
static __device__ __nv_bfloat16 g_th_h[BATCH * NPIX * CIDIM];  // [B][N][CI] (pre-scaled by log2e)
static __device__ __nv_bfloat16 g_th_l[BATCH * NPIX * CIDIM];
static __device__ __nv_bfloat16 g_ph_h[BATCH * NPIX * CIDIM];
static __device__ __nv_bfloat16 g_ph_l[BATCH * NPIX * CIDIM];
static __device__ __nv_bfloat16 g_gm_h[BATCH * CIDIM * NPIX];  // [B][CI][N]
static __device__ __nv_bfloat16 g_y_h [BATCH * NPIX * CIDIM];  // [B][N][CI]
static __device__ __nv_bfloat16 g_y_l [BATCH * NPIX * CIDIM];

// ---------------- PTX helpers (sm_80+ family-portable) ----------------
__device__ __forceinline__ uint32_t smem_to_u32(const void* p) {
    uint32_t a;
    asm("{ .reg .u64 t; cvta.to.shared.u64 t, %1; cvt.u32.u64 %0, t; }"
        : "=r"(a) : "l"(p));
    return a;
}
__device__ __forceinline__ void cp16(uint32_t dst, const void* src) {
    asm volatile("cp.async.cg.shared.global [%0], [%1], 16;" :: "r"(dst), "l"(src) : "memory");
}
#define CP_COMMIT() asm volatile("cp.async.commit_group;" ::: "memory")
#define CP_WAITG2() asm volatile("cp.async.wait_group 2;" ::: "memory")
#define CP_WAIT0()  asm volatile("cp.async.wait_group 0;" ::: "memory")
#define CP_WAIT1()  asm volatile("cp.async.wait_group 1;" ::: "memory")

__device__ __forceinline__ void ldsm4(uint32_t a, uint32_t& r0, uint32_t& r1,
                                      uint32_t& r2, uint32_t& r3) {
    asm volatile("ldmatrix.sync.aligned.m8n8.x4.shared.b16 {%0,%1,%2,%3}, [%4];"
                 : "=r"(r0), "=r"(r1), "=r"(r2), "=r"(r3) : "r"(a));
}
__device__ __forceinline__ void ldsm4t(uint32_t a, uint32_t& r0, uint32_t& r1,
                                       uint32_t& r2, uint32_t& r3) {
    asm volatile("ldmatrix.sync.aligned.m8n8.x4.trans.shared.b16 {%0,%1,%2,%3}, [%4];"
                 : "=r"(r0), "=r"(r1), "=r"(r2), "=r"(r3) : "r"(a));
}
__device__ __forceinline__ void mma16816(float* d, const uint32_t* a,
                                         uint32_t b0, uint32_t b1) {
    asm volatile("mma.sync.aligned.m16n8k16.row.col.f32.bf16.bf16.f32 "
                 "{%0,%1,%2,%3}, {%4,%5,%6,%7}, {%8,%9}, {%0,%1,%2,%3};"
                 : "+f"(d[0]), "+f"(d[1]), "+f"(d[2]), "+f"(d[3])
                 : "r"(a[0]), "r"(a[1]), "r"(a[2]), "r"(a[3]), "r"(b0), "r"(b1));
}
__device__ __forceinline__ uint32_t packbf2(float lo, float hi) {
    uint32_t r;
    asm("cvt.rn.satfinite.bf16x2.f32 %0, %1, %2;" : "=r"(r) : "f"(hi), "f"(lo));
    return r;
}
__device__ __forceinline__ float ex2f(float x) {
    float r;
    asm("ex2.approx.f32 %0, %1;" : "=f"(r) : "f"(x));
    return r;
}
__device__ __forceinline__ void split2(float v0, float v1, uint32_t& h, uint32_t& l) {
    __nv_bfloat16 h0 = __float2bfloat16(v0), h1 = __float2bfloat16(v1);
    float f0 = __bfloat162float(h0), f1 = __bfloat162float(h1);
    __nv_bfloat162 hh; hh.x = h0; hh.y = h1;
    __nv_bfloat162 ll; ll.x = __float2bfloat16(v0 - f0); ll.y = __float2bfloat16(v1 - f1);
    h = *(uint32_t*)&hh;
    l = *(uint32_t*)&ll;
}

// ================= convert kernels =================
__global__ __launch_bounds__(256) void xsplit_kernel(const float* __restrict__ x) {
    int i = blockIdx.x * 256 + threadIdx.x;
    float4 v = ((const float4*)x)[i];
    uint32_t h01, l01, h23, l23;
    split2(v.x, v.y, h01, l01);
    split2(v.z, v.w, h23, l23);
    ((uint2*)g_x_h)[i] = make_uint2(h01, h23);
    ((uint2*)g_x_l)[i] = make_uint2(l01, l23);
}
__global__ __launch_bounds__(256) void wsplit_kernel(
    const float* __restrict__ thw, const float* __restrict__ phw,
    const float* __restrict__ gw,  const float* __restrict__ Ww) {
    int idx = blockIdx.x * 256 + threadIdx.x;
    int seg = idx >> 15, loc = idx & 32767;
    const float* src = (seg == 0) ? thw : (seg == 1) ? phw : (seg == 2) ? gw : Ww;
    float v = src[loc];
    __nv_bfloat16 h = __float2bfloat16(v);
    g_wsp_h[idx] = h;
    g_wsp_l[idx] = __float2bfloat16(v - __bfloat162float(h));
}

// ================= HMMA projection =================
#define PJ_XSTR 272
#define PJ_WSTR 144
#define PJ_XH 0
#define PJ_XL 17408
#define PJ_WH 34816
#define PJ_WL 53248
#define PJ_STAGE 71680
#define PROJ_SMEM (2 * PJ_STAGE)

__global__ __launch_bounds__(256, 1) void proj_kernel(
    const float* __restrict__ th_b, const float* __restrict__ ph_b,
    const float* __restrict__ g_b)
{
    extern __shared__ char smem[];
    const uint32_t sb = smem_to_u32(smem);
    const int tid = threadIdx.x;
    const int w = tid >> 5, lane = tid & 31;
    const int wm = w & 3, wn = w >> 2;
    const int flavor = blockIdx.y;
    const int pt = blockIdx.x;
    const int bb = pt >> 5;
    const int n0 = (pt & 31) * 128;

    const __nv_bfloat16* xh = g_x_h + (size_t)bb * CDIM * NPIX + n0;
    const __nv_bfloat16* xl = g_x_l + (size_t)bb * CDIM * NPIX + n0;
    const __nv_bfloat16* wh = g_wsp_h + flavor * 32768;
    const __nv_bfloat16* wl = g_wsp_l + flavor * 32768;

    auto load_chunk = [&](int s, int k0) {
        uint32_t base = sb + s * PJ_STAGE;
        #pragma unroll
        for (int t = 0; t < 4; t++) {
            int q = tid + t * 256;
            int k = q >> 4, j = q & 15;
            uint32_t d = base + PJ_XH + k * PJ_XSTR + j * 16;
            size_t g = (size_t)(k0 + k) * NPIX + j * 8;
            cp16(d, xh + g);
            cp16(d + (PJ_XL - PJ_XH), xl + g);
        }
        #pragma unroll
        for (int t = 0; t < 4; t++) {
            int q = tid + t * 256;
            int o = q >> 3, j = q & 7;
            uint32_t d = base + PJ_WH + o * PJ_WSTR + j * 16;
            size_t g = (size_t)o * CDIM + k0 + j * 8;
            cp16(d, wh + g);
            cp16(d + (PJ_WL - PJ_WH), wl + g);
        }
    };
    load_chunk(0, 0);
    CP_COMMIT();

    uint32_t a_base, b_base, a_m16, a_kk, b_ng, b_kk, a_lo, b_lo;
    if (flavor < 2) {
        a_base = PJ_XH + (uint32_t)(((lane & 7) + ((lane >> 4) & 1) * 8) * PJ_XSTR
                                    + wm * 64 + ((lane >> 3) & 1) * 16);
        a_m16 = 32;               a_kk = 16 * PJ_XSTR;  a_lo = PJ_XL - PJ_XH;
        b_base = PJ_WH + (uint32_t)((wn * 64 + (lane & 7) + ((lane >> 4) & 1) * 8) * PJ_WSTR
                                    + ((lane >> 3) & 1) * 16);
        b_ng = 16 * PJ_WSTR;      b_kk = 32;            b_lo = PJ_WL - PJ_WH;
    } else {
        a_base = PJ_WH + (uint32_t)((wm * 32 + (lane & 15)) * PJ_WSTR + (lane >> 4) * 16);
        a_m16 = 16 * PJ_WSTR;     a_kk = 32;            a_lo = PJ_WL - PJ_WH;
        b_base = PJ_XH + (uint32_t)(((lane & 7) + ((lane >> 3) & 1) * 8) * PJ_XSTR
                                    + wn * 128 + (lane >> 4) * 16);
        b_ng = 32;                b_kk = 16 * PJ_XSTR;  b_lo = PJ_XL - PJ_XH;
    }

    float acc[2][8][4];
    #pragma unroll
    for (int i = 0; i < 2; i++)
        #pragma unroll
        for (int j = 0; j < 8; j++)
            #pragma unroll
            for (int q = 0; q < 4; q++) acc[i][j][q] = 0.f;

    #pragma unroll 1
    for (int ch = 0; ch < 4; ch++) {
        if (ch < 3) load_chunk((ch + 1) & 1, (ch + 1) * 64);
        CP_COMMIT();
        CP_WAIT1();
        __syncthreads();
        const uint32_t stb = sb + (ch & 1) * PJ_STAGE;
        #pragma unroll
        for (int kk = 0; kk < 4; kk++) {
            uint32_t aH[2][4], aL[2][4];
            #pragma unroll
            for (int m = 0; m < 2; m++) {
                uint32_t aa = stb + a_base + kk * a_kk + m * a_m16;
                if (flavor < 2) {
                    ldsm4t(aa,        aH[m][0], aH[m][1], aH[m][2], aH[m][3]);
                    ldsm4t(aa + a_lo, aL[m][0], aL[m][1], aL[m][2], aL[m][3]);
                } else {
                    ldsm4(aa,         aH[m][0], aH[m][1], aH[m][2], aH[m][3]);
                    ldsm4(aa + a_lo,  aL[m][0], aL[m][1], aL[m][2], aL[m][3]);
                }
            }
            #pragma unroll
            for (int ng = 0; ng < 4; ng++) {
                uint32_t bh0, bh1, bh2, bh3, bl0, bl1, bl2, bl3;
                uint32_t ba = stb + b_base + kk * b_kk + ng * b_ng;
                if (flavor < 2) {
                    ldsm4(ba,         bh0, bh1, bh2, bh3);
                    ldsm4(ba + b_lo,  bl0, bl1, bl2, bl3);
                } else {
                    ldsm4t(ba,        bh0, bh1, bh2, bh3);
                    ldsm4t(ba + b_lo, bl0, bl1, bl2, bl3);
                }
                #pragma unroll
                for (int m = 0; m < 2; m++) {
                    mma16816(acc[m][2 * ng],     aH[m], bh0, bh1);
                    mma16816(acc[m][2 * ng + 1], aH[m], bh2, bh3);
                    mma16816(acc[m][2 * ng],     aL[m], bh0, bh1);
                    mma16816(acc[m][2 * ng + 1], aL[m], bh2, bh3);
                    mma16816(acc[m][2 * ng],     aH[m], bl0, bl1);
                    mma16816(acc[m][2 * ng + 1], aH[m], bl2, bl3);
                }
            }
        }
        __syncthreads();
    }

    if (flavor < 2) {
        __nv_bfloat16* dh = (flavor == 0) ? g_th_h : g_ph_h;
        __nv_bfloat16* dl = (flavor == 0) ? g_th_l : g_ph_l;
        const float* bias = (flavor == 0) ? th_b : ph_b;
        const float scl = (flavor == 0) ? L2E : 1.0f;   // theta pre-scaled by log2e
        const int m_row = wm * 32 + (lane >> 2);
        const int o_col = wn * 64 + (lane & 3) * 2;
        #pragma unroll
        for (int m = 0; m < 2; m++) {
            #pragma unroll
            for (int n8 = 0; n8 < 8; n8++) {
                float2 bv = *(const float2*)&bias[o_col + n8 * 8];
                int pix = n0 + m_row + m * 16;
                size_t a0 = ((size_t)bb * NPIX + pix) * CIDIM + o_col + n8 * 8;
                uint32_t h, l;
                split2((acc[m][n8][0] + bv.x) * scl, (acc[m][n8][1] + bv.y) * scl, h, l);
                *(uint32_t*)&dh[a0] = h;
                *(uint32_t*)&dl[a0] = l;
                size_t a1 = a0 + (size_t)8 * CIDIM;
                split2((acc[m][n8][2] + bv.x) * scl, (acc[m][n8][3] + bv.y) * scl, h, l);
                *(uint32_t*)&dh[a1] = h;
                *(uint32_t*)&dl[a1] = l;
            }
        }
    } else {
        const int o_row = wm * 32 + (lane >> 2);
        const int p_col = wn * 64 + (lane & 3) * 2;
        #pragma unroll
        for (int m = 0; m < 2; m++) {
            int o = o_row + m * 16;
            float b0 = g_b[o], b1 = g_b[o + 8];
            #pragma unroll
            for (int n8 = 0; n8 < 8; n8++) {
                size_t a0 = ((size_t)bb * CIDIM + o) * NPIX + n0 + p_col + n8 * 8;
                *(uint32_t*)&g_gm_h[a0] =
                    packbf2(acc[m][n8][0] + b0, acc[m][n8][1] + b0);
                size_t a1 = a0 + (size_t)8 * NPIX;
                *(uint32_t*)&g_gm_h[a1] =
                    packbf2(acc[m][n8][2] + b1, acc[m][n8][3] + b1);
            }
        }
    }
}

// ================= HMMA flash attention (pipelined) =================
// SMEM: Q hi/lo persistent; K: 3 stages; G: 3 stages (PV deferred one iter
// keeps tiles jt..jt+2 live at prefetch-issue time -> 3 slots required).
#define QSTR 272
#define GSTR 144
#define OFF_QH 0
#define OFF_QL 34816
#define K_SLOT(s) (69632 + (s) * 34816)     // per slot: hi 17408 + lo 17408
#define KHL 17408
#define G_SLOT(s) (174080 + (s) * 18432)    // 3 slots
#define ATTN_SMEM 229376

__global__ __launch_bounds__(256, 1) void attn_kernel()
{
    extern __shared__ char smem[];
    const uint32_t sb = smem_to_u32(smem);
    const int tid = threadIdx.x;
    const int w = tid >> 5, lane = tid & 31;
    const int bb = blockIdx.y;
    const int i0 = blockIdx.x * QT;

    const __nv_bfloat16* qh = g_th_h + ((size_t)bb * NPIX + i0) * CIDIM;
    const __nv_bfloat16* ql = g_th_l + ((size_t)bb * NPIX + i0) * CIDIM;
    const __nv_bfloat16* phb = g_ph_h + (size_t)bb * NPIX * CIDIM;
    const __nv_bfloat16* plb = g_ph_l + (size_t)bb * NPIX * CIDIM;
    const __nv_bfloat16* ghb = g_gm_h + (size_t)bb * CIDIM * NPIX;

    auto load_k = [&](int slot, int j0) {
        uint32_t base = sb + K_SLOT(slot);
        #pragma unroll
        for (int t = 0; t < 4; t++) {           // 64 rows x 256B, hi+lo
            int q = tid + t * 256;
            int j = q >> 4, c = q & 15;
            uint32_t d = base + j * QSTR + c * 16;
            size_t g = (size_t)(j0 + j) * CIDIM + c * 8;
            cp16(d, phb + g);
            cp16(d + KHL, plb + g);
        }
    };
    auto load_g = [&](int slot, int j0) {
        uint32_t base = sb + G_SLOT(slot);
        #pragma unroll
        for (int t = 0; t < 4; t++) {           // 128 rows x 128B
            int q = tid + t * 256;
            int c = q >> 3, jc = q & 7;
            cp16(base + c * GSTR + jc * 16,
                 ghb + (size_t)c * NPIX + j0 + jc * 8);
        }
    };

    // prologue loads
    {
        #pragma unroll
        for (int t = 0; t < 8; t++) {           // Q hi/lo
            int q = tid + t * 256;
            int r = q >> 4, c = q & 15;
            uint32_t d = sb + OFF_QH + r * QSTR + c * 16;
            cp16(d, qh + r * CIDIM + c * 8);
            cp16(d + (OFF_QL - OFF_QH), ql + r * CIDIM + c * 8);
        }
        load_k(0, 0); load_g(0, 0); CP_COMMIT();
        load_k(1, 64); load_g(1, 64); CP_COMMIT();
        load_k(2, 128); CP_COMMIT();
    }

    const uint32_t a_lane = (uint32_t)((lane & 15) * QSTR + (lane >> 4) * 16);
    const uint32_t aq_base = sb + OFF_QH + (uint32_t)(w * 16) * QSTR + a_lane;
    const uint32_t al_base = aq_base + (OFF_QL - OFF_QH);
    const int b_row  = (lane & 7) + ((lane >> 4) & 1) * 8;
    const int b_byte = ((lane >> 3) & 1) * 16;
    const uint32_t b_off = (uint32_t)(b_row * QSTR + b_byte);
    const uint32_t g_off = (uint32_t)(b_row * GSTR + b_byte);

    float oacc[16][4];
    #pragma unroll
    for (int i = 0; i < 16; i++)
        #pragma unroll
        for (int j = 0; j < 4; j++) oacc[i][j] = 0.f;
    float den0 = 0.f, den1 = 0.f;
    uint32_t pf_a[2][4], pf_b[2][4];

    #pragma unroll 1
    for (int jt = 0; jt < NJT; jt++) {
        CP_WAITG2();
        __syncthreads();

        // ---- PV(jt-1): O += P(jt-1) @ G(jt-1)^T ----
        if (jt > 0) {
            const uint32_t gB = sb + G_SLOT((jt - 1) % 3) + g_off;
            #pragma unroll
            for (int kkj = 0; kkj < 2; kkj++) {
                #pragma unroll
                for (int cb = 0; cb < 8; cb++) {
                    uint32_t bh0, bh1, bh2, bh3;
                    ldsm4(gB + (uint32_t)(cb * 16 * GSTR + kkj * 32), bh0, bh1, bh2, bh3);
                    mma16816(oacc[2 * cb],     pf_a[kkj], bh0, bh1);
                    mma16816(oacc[2 * cb + 1], pf_a[kkj], bh2, bh3);
                }
            }
            #pragma unroll
            for (int kkj = 0; kkj < 2; kkj++) {
                #pragma unroll
                for (int cb = 0; cb < 8; cb++) {
                    uint32_t bh0, bh1, bh2, bh3;
                    ldsm4(gB + (uint32_t)(cb * 16 * GSTR + (kkj + 2) * 32), bh0, bh1, bh2, bh3);
                    mma16816(oacc[2 * cb],     pf_b[kkj], bh0, bh1);
                    mma16816(oacc[2 * cb + 1], pf_b[kkj], bh2, bh3);
                }
            }
        }

        // ---- S(jt), half a (cols 0..31) ----
        const uint32_t kB = sb + K_SLOT(jt % 3) + b_off;
        float sacc_a[4][4], sacc_b[4][4];
        #pragma unroll
        for (int i = 0; i < 4; i++)
            #pragma unroll
            for (int j = 0; j < 4; j++) { sacc_a[i][j] = 0.f; sacc_b[i][j] = 0.f; }

        #pragma unroll
        for (int kk = 0; kk < 8; kk++) {
            uint32_t aq[4], al[4];
            ldsm4(aq_base + kk * 32, aq[0], aq[1], aq[2], aq[3]);
            ldsm4(al_base + kk * 32, al[0], al[1], al[2], al[3]);
            #pragma unroll
            for (int nb4 = 0; nb4 < 2; nb4++) {
                uint32_t bh0, bh1, bh2, bh3, bl0, bl1, bl2, bl3;
                uint32_t ka = kB + (uint32_t)(nb4 * 16 * QSTR + kk * 32);
                ldsm4(ka, bh0, bh1, bh2, bh3);
                ldsm4(ka + KHL, bl0, bl1, bl2, bl3);
                mma16816(sacc_a[2 * nb4],     aq, bh0, bh1);
                mma16816(sacc_a[2 * nb4 + 1], aq, bh2, bh3);
                mma16816(sacc_a[2 * nb4],     al, bh0, bh1);
                mma16816(sacc_a[2 * nb4 + 1], al, bh2, bh3);
                mma16816(sacc_a[2 * nb4],     aq, bl0, bl1);
                mma16816(sacc_a[2 * nb4 + 1], aq, bl2, bl3);
            }
        }

        // ---- exp half a (independent of S half b -> overlaps) ----
        #pragma unroll
        for (int nb = 0; nb < 4; nb++) {
            float e0 = ex2f(sacc_a[nb][0]);
            float e1 = ex2f(sacc_a[nb][1]);
            float e2 = ex2f(sacc_a[nb][2]);
            float e3 = ex2f(sacc_a[nb][3]);
            den0 += e0 + e1;
            den1 += e2 + e3;
            int kkj = nb >> 1, half = (nb & 1) * 2;
            pf_a[kkj][half]     = packbf2(e0, e1);
            pf_a[kkj][half + 1] = packbf2(e2, e3);
        }

        // ---- S(jt), half b (cols 32..63) ----
        #pragma unroll
        for (int kk = 0; kk < 8; kk++) {
            uint32_t aq[4], al[4];
            ldsm4(aq_base + kk * 32, aq[0], aq[1], aq[2], aq[3]);
            ldsm4(al_base + kk * 32, al[0], al[1], al[2], al[3]);
            #pragma unroll
            for (int nb4 = 0; nb4 < 2; nb4++) {
                uint32_t bh0, bh1, bh2, bh3, bl0, bl1, bl2, bl3;
                uint32_t ka = kB + (uint32_t)((nb4 + 2) * 16 * QSTR + kk * 32);
                ldsm4(ka, bh0, bh1, bh2, bh3);
                ldsm4(ka + KHL, bl0, bl1, bl2, bl3);
                mma16816(sacc_b[2 * nb4],     aq, bh0, bh1);
                mma16816(sacc_b[2 * nb4 + 1], aq, bh2, bh3);
                mma16816(sacc_b[2 * nb4],     al, bh0, bh1);
                mma16816(sacc_b[2 * nb4 + 1], al, bh2, bh3);
                mma16816(sacc_b[2 * nb4],     aq, bl0, bl1);
                mma16816(sacc_b[2 * nb4 + 1], aq, bl2, bl3);
            }
        }

        __syncthreads();   // all warps done with K[jt%3] & G[(jt-1)%3] reads
        if (jt + 3 < NJT) load_k(jt % 3, (jt + 3) * JT);
        if (jt + 2 < NJT) load_g((jt + 2) % 3, (jt + 2) * JT);
        CP_COMMIT();

        // ---- exp half b (tail; consumed by PV next iteration) ----
        #pragma unroll
        for (int nb = 0; nb < 4; nb++) {
            float e0 = ex2f(sacc_b[nb][0]);
            float e1 = ex2f(sacc_b[nb][1]);
            float e2 = ex2f(sacc_b[nb][2]);
            float e3 = ex2f(sacc_b[nb][3]);
            den0 += e0 + e1;
            den1 += e2 + e3;
            int kkj = nb >> 1, half = (nb & 1) * 2;
            pf_b[kkj][half]     = packbf2(e0, e1);
            pf_b[kkj][half + 1] = packbf2(e2, e3);
        }
    }

    // ---- final PV(NJT-1) ----
    {
        const uint32_t gB = sb + G_SLOT((NJT - 1) % 3) + g_off;
        #pragma unroll
        for (int kkj = 0; kkj < 2; kkj++) {
            #pragma unroll
            for (int cb = 0; cb < 8; cb++) {
                uint32_t bh0, bh1, bh2, bh3;
                ldsm4(gB + (uint32_t)(cb * 16 * GSTR + kkj * 32), bh0, bh1, bh2, bh3);
                mma16816(oacc[2 * cb],     pf_a[kkj], bh0, bh1);
                mma16816(oacc[2 * cb + 1], pf_a[kkj], bh2, bh3);
            }
        }
        #pragma unroll
        for (int kkj = 0; kkj < 2; kkj++) {
            #pragma unroll
            for (int cb = 0; cb < 8; cb++) {
                uint32_t bh0, bh1, bh2, bh3;
                ldsm4(gB + (uint32_t)(cb * 16 * GSTR + (kkj + 2) * 32), bh0, bh1, bh2, bh3);
                mma16816(oacc[2 * cb],     pf_b[kkj], bh0, bh1);
                mma16816(oacc[2 * cb + 1], pf_b[kkj], bh2, bh3);
            }
        }
    }

    den0 += __shfl_xor_sync(0xFFFFFFFF, den0, 1);
    den0 += __shfl_xor_sync(0xFFFFFFFF, den0, 2);
    den1 += __shfl_xor_sync(0xFFFFFFFF, den1, 1);
    den1 += __shfl_xor_sync(0xFFFFFFFF, den1, 2);
    const float inv0 = 1.0f / den0;
    const float inv1 = 1.0f / den1;

    const int r0 = i0 + w * 16 + (lane >> 2);
    size_t base0 = ((size_t)bb * NPIX + r0) * CIDIM + (lane & 3) * 2;
    #pragma unroll
    for (int cb = 0; cb < 16; cb++) {
        uint32_t h, l;
        split2(oacc[cb][0] * inv0, oacc[cb][1] * inv0, h, l);
        *(uint32_t*)&g_y_h[base0 + cb * 8] = h;
        *(uint32_t*)&g_y_l[base0 + cb * 8] = l;
        split2(oacc[cb][2] * inv1, oacc[cb][3] * inv1, h, l);
        *(uint32_t*)&g_y_h[base0 + 8 * CIDIM + cb * 8] = h;
        *(uint32_t*)&g_y_l[base0 + 8 * CIDIM + cb * 8] = l;
    }
}

// ================= HMMA outproj: out = W_w @ y + b + x =================
#define OP_STR 272
#define OP_WH 0
#define OP_WL 34816
#define OP_YH 69632
#define OP_YL 104448
#define OP_SMEM 139264

__global__ __launch_bounds__(256, 1) void outproj_kernel(
    const float* __restrict__ Wb, const float* __restrict__ x,
    float* __restrict__ out)
{
    extern __shared__ char smem[];
    const uint32_t sb = smem_to_u32(smem);
    const int tid = threadIdx.x;
    const int w = tid >> 5, lane = tid & 31;
    const int wm = w & 3, wn = w >> 2;
    const int pt = blockIdx.x;
    const int c0 = blockIdx.y * 128;
    const int bb = pt >> 5;
    const int n0 = (pt & 31) * 128;

    const __nv_bfloat16* wwh = g_wsp_h + 3 * 32768;
    const __nv_bfloat16* wwl = g_wsp_l + 3 * 32768;
    const __nv_bfloat16* yh = g_y_h + ((size_t)bb * NPIX + n0) * CIDIM;
    const __nv_bfloat16* yl = g_y_l + ((size_t)bb * NPIX + n0) * CIDIM;

    #pragma unroll
    for (int t = 0; t < 8; t++) {
        int q = tid + t * 256;
        int r = q >> 4, j = q & 15;
        uint32_t d = sb + OP_WH + r * OP_STR + j * 16;
        size_t g = (size_t)(c0 + r) * CIDIM + j * 8;
        cp16(d, wwh + g);
        cp16(d + (OP_WL - OP_WH), wwl + g);
    }
    #pragma unroll
    for (int t = 0; t < 8; t++) {
        int q = tid + t * 256;
        int r = q >> 4, j = q & 15;
        uint32_t d = sb + OP_YH + r * OP_STR + j * 16;
        size_t g = (size_t)r * CIDIM + j * 8;
        cp16(d, yh + g);
        cp16(d + (OP_YL - OP_YH), yl + g);
    }
    CP_COMMIT();
    CP_WAIT0();
    __syncthreads();

    const uint32_t a_base = sb + OP_WH +
        (uint32_t)((wm * 32 + (lane & 15)) * OP_STR + (lane >> 4) * 16);
    const uint32_t b_base = sb + OP_YH +
        (uint32_t)((wn * 64 + (lane & 7) + ((lane >> 4) & 1) * 8) * OP_STR
                   + ((lane >> 3) & 1) * 16);

    float acc[2][8][4];
    #pragma unroll
    for (int i = 0; i < 2; i++)
        #pragma unroll
        for (int j = 0; j < 8; j++)
            #pragma unroll
            for (int q = 0; q < 4; q++) acc[i][j][q] = 0.f;

    #pragma unroll
    for (int kk = 0; kk < 8; kk++) {
        uint32_t aH[2][4], aL[2][4];
        #pragma unroll
        for (int m = 0; m < 2; m++) {
            uint32_t aa = a_base + kk * 32 + m * 16 * OP_STR;
            ldsm4(aa,                  aH[m][0], aH[m][1], aH[m][2], aH[m][3]);
            ldsm4(aa + (OP_WL - OP_WH), aL[m][0], aL[m][1], aL[m][2], aL[m][3]);
        }
        #pragma unroll
        for (int ng = 0; ng < 4; ng++) {
            uint32_t bh0, bh1, bh2, bh3, bl0, bl1, bl2, bl3;
            uint32_t ba = b_base + kk * 32 + ng * 16 * OP_STR;
            ldsm4(ba,                  bh0, bh1, bh2, bh3);
            ldsm4(ba + (OP_YL - OP_YH), bl0, bl1, bl2, bl3);
            #pragma unroll
            for (int m = 0; m < 2; m++) {
                mma16816(acc[m][2 * ng],     aH[m], bh0, bh1);
                mma16816(acc[m][2 * ng + 1], aH[m], bh2, bh3);
                mma16816(acc[m][2 * ng],     aL[m], bh0, bh1);
                mma16816(acc[m][2 * ng + 1], aL[m], bh2, bh3);
                mma16816(acc[m][2 * ng],     aH[m], bl0, bl1);
                mma16816(acc[m][2 * ng + 1], aH[m], bl2, bl3);
            }
        }
    }

    const int c_row = c0 + wm * 32 + (lane >> 2);
    const int p_col = wn * 64 + (lane & 3) * 2;
    #pragma unroll
    for (int m = 0; m < 2; m++) {
        int c = c_row + m * 16;
        float b0 = Wb[c], b1 = Wb[c + 8];
        #pragma unroll
        for (int n8 = 0; n8 < 8; n8++) {
            size_t a0 = ((size_t)bb * CDIM + c) * NPIX + n0 + p_col + n8 * 8;
            float2 xv = *(const float2*)&x[a0];
            *(float2*)&out[a0] = make_float2(acc[m][n8][0] + b0 + xv.x,
                                             acc[m][n8][1] + b0 + xv.y);
            size_t a1 = a0 + (size_t)8 * NPIX;
            float2 xv1 = *(const float2*)&x[a1];
            *(float2*)&out[a1] = make_float2(acc[m][n8][2] + b1 + xv1.x,
                                             acc[m][n8][3] + b1 + xv1.y);
        }
    }
}

extern "C" void kernel_launch(void* const* d_in, const int* in_sizes, int n_in,
                              void* d_out, int out_size) {
    const float* x    = (const float*)d_in[0];
    const float* g_w  = (const float*)d_in[1];
    const float* g_b  = (const float*)d_in[2];
    const float* th_w = (const float*)d_in[3];
    const float* th_b = (const float*)d_in[4];
    const float* ph_w = (const float*)d_in[5];
    const float* ph_b = (const float*)d_in[6];
    const float* W_w  = (const float*)d_in[7];
    const float* W_b  = (const float*)d_in[8];
    float* out = (float*)d_out;

    cudaFuncSetAttribute(proj_kernel,
                         cudaFuncAttributeMaxDynamicSharedMemorySize, PROJ_SMEM);
    cudaFuncSetAttribute(attn_kernel,
                         cudaFuncAttributeMaxDynamicSharedMemorySize, ATTN_SMEM);
    cudaFuncSetAttribute(outproj_kernel,
                         cudaFuncAttributeMaxDynamicSharedMemorySize, OP_SMEM);

    xsplit_kernel<<<BATCH * CDIM * NPIX / 4 / 256, 256>>>(x);
    wsplit_kernel<<<4 * 32768 / 256, 256>>>(th_w, ph_w, g_w, W_w);
    proj_kernel<<<dim3(BATCH * NPIX / 128, 3), 256, PROJ_SMEM>>>(th_b, ph_b, g_b);
    attn_kernel<<<dim3(NPIX / QT, BATCH), 256, ATTN_SMEM>>>();
    outproj_kernel<<<dim3(BATCH * NPIX / 128, CDIM / 128), 256, OP_SMEM>>>(W_b, x, out);
}

// round 13
// speedup vs baseline: 1.0774x; 1.0774x over previous
#include <cuda_runtime.h>
#include <cuda_bf16.h>
#include <cstdint>
#include <cstddef>

#define BATCH 8
#define CDIM 256
#define CIDIM 128
#define NPIX 4096
#define QT 128
#define JT 64
#define KSPLIT 4
#define NSPL (NPIX / KSPLIT)          // keys per split = 1024
#define NJT_PER (NSPL / JT)           // 16 j-tiles per CTA
#define L2E 1.4426950408889634f

// ---------------- scratch (__device__ globals; no allocation) ----------------
static __device__ __nv_bfloat16 g_x_h [BATCH * CDIM * NPIX];
static __device__ __nv_bfloat16 g_x_l [BATCH * CDIM * NPIX];
static __device__ __nv_bfloat16 g_wsp_h[4 * 32768];
static __device__ __nv_bfloat16 g_wsp_l[4 * 32768];
static __device__ __nv_bfloat16 g_th_h[BATCH * NPIX * CIDIM];  // pre-scaled by log2e
static __device__ __nv_bfloat16 g_th_l[BATCH * NPIX * CIDIM];
static __device__ __nv_bfloat16 g_ph_h[BATCH * NPIX * CIDIM];
static __device__ __nv_bfloat16 g_ph_l[BATCH * NPIX * CIDIM];
static __device__ __nv_bfloat16 g_gm_h[BATCH * CIDIM * NPIX];
static __device__ __nv_bfloat16 g_y_h [BATCH * NPIX * CIDIM];
static __device__ __nv_bfloat16 g_y_l [BATCH * NPIX * CIDIM];
static __device__ float g_o  [KSPLIT * BATCH * NPIX * CIDIM]; // partial O
static __device__ float g_den[KSPLIT * BATCH * NPIX];          // partial den

// ---------------- PTX helpers ----------------
__device__ __forceinline__ uint32_t smem_to_u32(const void* p) {
    uint32_t a;
    asm("{ .reg .u64 t; cvta.to.shared.u64 t, %1; cvt.u32.u64 %0, t; }"
        : "=r"(a) : "l"(p));
    return a;
}
__device__ __forceinline__ void cp16(uint32_t dst, const void* src) {
    asm volatile("cp.async.cg.shared.global [%0], [%1], 16;" :: "r"(dst), "l"(src) : "memory");
}
#define CP_COMMIT() asm volatile("cp.async.commit_group;" ::: "memory")
#define CP_WAIT0()  asm volatile("cp.async.wait_group 0;" ::: "memory")
#define CP_WAIT1()  asm volatile("cp.async.wait_group 1;" ::: "memory")

__device__ __forceinline__ void ldsm4(uint32_t a, uint32_t& r0, uint32_t& r1,
                                      uint32_t& r2, uint32_t& r3) {
    asm volatile("ldmatrix.sync.aligned.m8n8.x4.shared.b16 {%0,%1,%2,%3}, [%4];"
                 : "=r"(r0), "=r"(r1), "=r"(r2), "=r"(r3) : "r"(a));
}
__device__ __forceinline__ void ldsm4t(uint32_t a, uint32_t& r0, uint32_t& r1,
                                       uint32_t& r2, uint32_t& r3) {
    asm volatile("ldmatrix.sync.aligned.m8n8.x4.trans.shared.b16 {%0,%1,%2,%3}, [%4];"
                 : "=r"(r0), "=r"(r1), "=r"(r2), "=r"(r3) : "r"(a));
}
__device__ __forceinline__ void mma16816(float* d, const uint32_t* a,
                                         uint32_t b0, uint32_t b1) {
    asm volatile("mma.sync.aligned.m16n8k16.row.col.f32.bf16.bf16.f32 "
                 "{%0,%1,%2,%3}, {%4,%5,%6,%7}, {%8,%9}, {%0,%1,%2,%3};"
                 : "+f"(d[0]), "+f"(d[1]), "+f"(d[2]), "+f"(d[3])
                 : "r"(a[0]), "r"(a[1]), "r"(a[2]), "r"(a[3]), "r"(b0), "r"(b1));
}
__device__ __forceinline__ uint32_t packbf2(float lo, float hi) {
    uint32_t r;
    asm("cvt.rn.satfinite.bf16x2.f32 %0, %1, %2;" : "=r"(r) : "f"(hi), "f"(lo));
    return r;
}
__device__ __forceinline__ float ex2f(float x) {
    float r;
    asm("ex2.approx.f32 %0, %1;" : "=f"(r) : "f"(x));
    return r;
}
__device__ __forceinline__ void split2(float v0, float v1, uint32_t& h, uint32_t& l) {
    __nv_bfloat16 h0 = __float2bfloat16(v0), h1 = __float2bfloat16(v1);
    float f0 = __bfloat162float(h0), f1 = __bfloat162float(h1);
    __nv_bfloat162 hh; hh.x = h0; hh.y = h1;
    __nv_bfloat162 ll; ll.x = __float2bfloat16(v0 - f0); ll.y = __float2bfloat16(v1 - f1);
    h = *(uint32_t*)&hh;
    l = *(uint32_t*)&ll;
}

// ================= convert kernels =================
__global__ __launch_bounds__(256) void xsplit_kernel(const float* __restrict__ x) {
    int i = blockIdx.x * 256 + threadIdx.x;
    float4 v = ((const float4*)x)[i];
    uint32_t h01, l01, h23, l23;
    split2(v.x, v.y, h01, l01);
    split2(v.z, v.w, h23, l23);
    ((uint2*)g_x_h)[i] = make_uint2(h01, h23);
    ((uint2*)g_x_l)[i] = make_uint2(l01, l23);
}
__global__ __launch_bounds__(256) void wsplit_kernel(
    const float* __restrict__ thw, const float* __restrict__ phw,
    const float* __restrict__ gw,  const float* __restrict__ Ww) {
    int idx = blockIdx.x * 256 + threadIdx.x;
    int seg = idx >> 15, loc = idx & 32767;
    const float* src = (seg == 0) ? thw : (seg == 1) ? phw : (seg == 2) ? gw : Ww;
    float v = src[loc];
    __nv_bfloat16 h = __float2bfloat16(v);
    g_wsp_h[idx] = h;
    g_wsp_l[idx] = __float2bfloat16(v - __bfloat162float(h));
}

// ================= HMMA projection =================
#define PJ_XSTR 272
#define PJ_WSTR 144
#define PJ_XH 0
#define PJ_XL 17408
#define PJ_WH 34816
#define PJ_WL 53248
#define PJ_STAGE 71680
#define PROJ_SMEM (2 * PJ_STAGE)

__global__ __launch_bounds__(256, 1) void proj_kernel(
    const float* __restrict__ th_b, const float* __restrict__ ph_b,
    const float* __restrict__ g_b)
{
    extern __shared__ char smem[];
    const uint32_t sb = smem_to_u32(smem);
    const int tid = threadIdx.x;
    const int w = tid >> 5, lane = tid & 31;
    const int wm = w & 3, wn = w >> 2;
    const int flavor = blockIdx.y;
    const int pt = blockIdx.x;
    const int bb = pt >> 5;
    const int n0 = (pt & 31) * 128;

    const __nv_bfloat16* xh = g_x_h + (size_t)bb * CDIM * NPIX + n0;
    const __nv_bfloat16* xl = g_x_l + (size_t)bb * CDIM * NPIX + n0;
    const __nv_bfloat16* wh = g_wsp_h + flavor * 32768;
    const __nv_bfloat16* wl = g_wsp_l + flavor * 32768;

    auto load_chunk = [&](int s, int k0) {
        uint32_t base = sb + s * PJ_STAGE;
        #pragma unroll
        for (int t = 0; t < 4; t++) {
            int q = tid + t * 256;
            int k = q >> 4, j = q & 15;
            uint32_t d = base + PJ_XH + k * PJ_XSTR + j * 16;
            size_t g = (size_t)(k0 + k) * NPIX + j * 8;
            cp16(d, xh + g);
            cp16(d + (PJ_XL - PJ_XH), xl + g);
        }
        #pragma unroll
        for (int t = 0; t < 4; t++) {
            int q = tid + t * 256;
            int o = q >> 3, j = q & 7;
            uint32_t d = base + PJ_WH + o * PJ_WSTR + j * 16;
            size_t g = (size_t)o * CDIM + k0 + j * 8;
            cp16(d, wh + g);
            cp16(d + (PJ_WL - PJ_WH), wl + g);
        }
    };
    load_chunk(0, 0);
    CP_COMMIT();

    uint32_t a_base, b_base, a_m16, a_kk, b_ng, b_kk, a_lo, b_lo;
    if (flavor < 2) {
        a_base = PJ_XH + (uint32_t)(((lane & 7) + ((lane >> 4) & 1) * 8) * PJ_XSTR
                                    + wm * 64 + ((lane >> 3) & 1) * 16);
        a_m16 = 32;               a_kk = 16 * PJ_XSTR;  a_lo = PJ_XL - PJ_XH;
        b_base = PJ_WH + (uint32_t)((wn * 64 + (lane & 7) + ((lane >> 4) & 1) * 8) * PJ_WSTR
                                    + ((lane >> 3) & 1) * 16);
        b_ng = 16 * PJ_WSTR;      b_kk = 32;            b_lo = PJ_WL - PJ_WH;
    } else {
        a_base = PJ_WH + (uint32_t)((wm * 32 + (lane & 15)) * PJ_WSTR + (lane >> 4) * 16);
        a_m16 = 16 * PJ_WSTR;     a_kk = 32;            a_lo = PJ_WL - PJ_WH;
        b_base = PJ_XH + (uint32_t)(((lane & 7) + ((lane >> 3) & 1) * 8) * PJ_XSTR
                                    + wn * 128 + (lane >> 4) * 16);
        b_ng = 32;                b_kk = 16 * PJ_XSTR;  b_lo = PJ_XL - PJ_XH;
    }

    float acc[2][8][4];
    #pragma unroll
    for (int i = 0; i < 2; i++)
        #pragma unroll
        for (int j = 0; j < 8; j++)
            #pragma unroll
            for (int q = 0; q < 4; q++) acc[i][j][q] = 0.f;

    #pragma unroll 1
    for (int ch = 0; ch < 4; ch++) {
        if (ch < 3) load_chunk((ch + 1) & 1, (ch + 1) * 64);
        CP_COMMIT();
        CP_WAIT1();
        __syncthreads();
        const uint32_t stb = sb + (ch & 1) * PJ_STAGE;
        #pragma unroll
        for (int kk = 0; kk < 4; kk++) {
            uint32_t aH[2][4], aL[2][4];
            #pragma unroll
            for (int m = 0; m < 2; m++) {
                uint32_t aa = stb + a_base + kk * a_kk + m * a_m16;
                if (flavor < 2) {
                    ldsm4t(aa,        aH[m][0], aH[m][1], aH[m][2], aH[m][3]);
                    ldsm4t(aa + a_lo, aL[m][0], aL[m][1], aL[m][2], aL[m][3]);
                } else {
                    ldsm4(aa,         aH[m][0], aH[m][1], aH[m][2], aH[m][3]);
                    ldsm4(aa + a_lo,  aL[m][0], aL[m][1], aL[m][2], aL[m][3]);
                }
            }
            #pragma unroll
            for (int ng = 0; ng < 4; ng++) {
                uint32_t bh0, bh1, bh2, bh3, bl0, bl1, bl2, bl3;
                uint32_t ba = stb + b_base + kk * b_kk + ng * b_ng;
                if (flavor < 2) {
                    ldsm4(ba,         bh0, bh1, bh2, bh3);
                    ldsm4(ba + b_lo,  bl0, bl1, bl2, bl3);
                } else {
                    ldsm4t(ba,        bh0, bh1, bh2, bh3);
                    ldsm4t(ba + b_lo, bl0, bl1, bl2, bl3);
                }
                #pragma unroll
                for (int m = 0; m < 2; m++) {
                    mma16816(acc[m][2 * ng],     aH[m], bh0, bh1);
                    mma16816(acc[m][2 * ng + 1], aH[m], bh2, bh3);
                    mma16816(acc[m][2 * ng],     aL[m], bh0, bh1);
                    mma16816(acc[m][2 * ng + 1], aL[m], bh2, bh3);
                    mma16816(acc[m][2 * ng],     aH[m], bl0, bl1);
                    mma16816(acc[m][2 * ng + 1], aH[m], bl2, bl3);
                }
            }
        }
        __syncthreads();
    }

    if (flavor < 2) {
        __nv_bfloat16* dh = (flavor == 0) ? g_th_h : g_ph_h;
        __nv_bfloat16* dl = (flavor == 0) ? g_th_l : g_ph_l;
        const float* bias = (flavor == 0) ? th_b : ph_b;
        const float scl = (flavor == 0) ? L2E : 1.0f;
        const int m_row = wm * 32 + (lane >> 2);
        const int o_col = wn * 64 + (lane & 3) * 2;
        #pragma unroll
        for (int m = 0; m < 2; m++) {
            #pragma unroll
            for (int n8 = 0; n8 < 8; n8++) {
                float2 bv = *(const float2*)&bias[o_col + n8 * 8];
                int pix = n0 + m_row + m * 16;
                size_t a0 = ((size_t)bb * NPIX + pix) * CIDIM + o_col + n8 * 8;
                uint32_t h, l;
                split2((acc[m][n8][0] + bv.x) * scl, (acc[m][n8][1] + bv.y) * scl, h, l);
                *(uint32_t*)&dh[a0] = h;
                *(uint32_t*)&dl[a0] = l;
                size_t a1 = a0 + (size_t)8 * CIDIM;
                split2((acc[m][n8][2] + bv.x) * scl, (acc[m][n8][3] + bv.y) * scl, h, l);
                *(uint32_t*)&dh[a1] = h;
                *(uint32_t*)&dl[a1] = l;
            }
        }
    } else {
        const int o_row = wm * 32 + (lane >> 2);
        const int p_col = wn * 64 + (lane & 3) * 2;
        #pragma unroll
        for (int m = 0; m < 2; m++) {
            int o = o_row + m * 16;
            float b0 = g_b[o], b1 = g_b[o + 8];
            #pragma unroll
            for (int n8 = 0; n8 < 8; n8++) {
                size_t a0 = ((size_t)bb * CIDIM + o) * NPIX + n0 + p_col + n8 * 8;
                *(uint32_t*)&g_gm_h[a0] =
                    packbf2(acc[m][n8][0] + b0, acc[m][n8][1] + b0);
                size_t a1 = a0 + (size_t)8 * NPIX;
                *(uint32_t*)&g_gm_h[a1] =
                    packbf2(acc[m][n8][2] + b1, acc[m][n8][3] + b1);
            }
        }
    }
}

// ================= HMMA flash attention (R6 structure, 4-way key split) =====
#define QSTR 272
#define GSTR 144
#define OFF_QH 0
#define OFF_QL 34816
#define OFF_ST0 69632
#define ST_KH 0
#define ST_KL 17408
#define ST_GH 34816
#define STAGE_SZ 53248
#define ATTN_SMEM 176128

__global__ __launch_bounds__(256, 1) void attn_kernel()
{
    extern __shared__ char smem[];
    const uint32_t sb = smem_to_u32(smem);
    const int tid = threadIdx.x;
    const int w = tid >> 5, lane = tid & 31;
    const int bb = blockIdx.y;
    const int i0 = blockIdx.x * QT;
    const int ks = blockIdx.z;
    const int jbase = ks * NSPL;

    const __nv_bfloat16* qh = g_th_h + ((size_t)bb * NPIX + i0) * CIDIM;
    const __nv_bfloat16* ql = g_th_l + ((size_t)bb * NPIX + i0) * CIDIM;
    const __nv_bfloat16* phb = g_ph_h + (size_t)bb * NPIX * CIDIM;
    const __nv_bfloat16* plb = g_ph_l + (size_t)bb * NPIX * CIDIM;
    const __nv_bfloat16* ghb = g_gm_h + (size_t)bb * CIDIM * NPIX;

    #pragma unroll
    for (int t = 0; t < 8; t++) {
        int q = tid + t * 256;
        int r = q >> 4, c = q & 15;
        uint32_t d = sb + OFF_QH + r * QSTR + c * 16;
        cp16(d, qh + r * CIDIM + c * 8);
        cp16(d + (OFF_QL - OFF_QH), ql + r * CIDIM + c * 8);
    }

    auto load_stage = [&](int s, int j0) {
        uint32_t base = sb + OFF_ST0 + s * STAGE_SZ;
        #pragma unroll
        for (int t = 0; t < 4; t++) {           // K hi/lo: 64 rows x 256B
            int q = tid + t * 256;
            int j = q >> 4, c = q & 15;
            uint32_t d = base + ST_KH + j * QSTR + c * 16;
            size_t g = (size_t)(j0 + j) * CIDIM + c * 8;
            cp16(d, phb + g);
            cp16(d + (ST_KL - ST_KH), plb + g);
        }
        #pragma unroll
        for (int t = 0; t < 4; t++) {           // G hi: 128 rows x 128B
            int q = tid + t * 256;
            int c = q >> 3, jc = q & 7;
            cp16(base + ST_GH + c * GSTR + jc * 16,
                 ghb + (size_t)c * NPIX + j0 + jc * 8);
        }
    };
    load_stage(0, jbase);
    CP_COMMIT();

    const uint32_t a_lane = (uint32_t)((lane & 15) * QSTR + (lane >> 4) * 16);
    const uint32_t aq_base = sb + OFF_QH + (uint32_t)(w * 16) * QSTR + a_lane;
    const uint32_t al_base = aq_base + (OFF_QL - OFF_QH);
    const int b_row  = (lane & 7) + ((lane >> 4) & 1) * 8;
    const int b_byte = ((lane >> 3) & 1) * 16;

    float oacc[16][4];
    #pragma unroll
    for (int i = 0; i < 16; i++)
        #pragma unroll
        for (int j = 0; j < 4; j++) oacc[i][j] = 0.f;
    float den0 = 0.f, den1 = 0.f;

    for (int jt = 0; jt < NJT_PER; jt++) {
        const int s = jt & 1;
        if (jt + 1 < NJT_PER) load_stage(s ^ 1, jbase + (jt + 1) * JT);
        CP_COMMIT();
        CP_WAIT1();
        __syncthreads();

        const uint32_t stb = sb + OFF_ST0 + s * STAGE_SZ;
        const uint32_t kB = stb + ST_KH + (uint32_t)(b_row * QSTR + b_byte);
        const uint32_t gB = stb + ST_GH + (uint32_t)(b_row * GSTR + b_byte);

        float sacc[8][4];
        #pragma unroll
        for (int i = 0; i < 8; i++)
            #pragma unroll
            for (int j = 0; j < 4; j++) sacc[i][j] = 0.f;

        #pragma unroll
        for (int kk = 0; kk < 8; kk++) {
            uint32_t aq[4], al[4];
            ldsm4(aq_base + kk * 32, aq[0], aq[1], aq[2], aq[3]);
            ldsm4(al_base + kk * 32, al[0], al[1], al[2], al[3]);
            #pragma unroll
            for (int nb4 = 0; nb4 < 4; nb4++) {
                uint32_t bh0, bh1, bh2, bh3, bl0, bl1, bl2, bl3;
                uint32_t ka = kB + (uint32_t)(nb4 * 16 * QSTR + kk * 32);
                ldsm4(ka, bh0, bh1, bh2, bh3);
                ldsm4(ka + (ST_KL - ST_KH), bl0, bl1, bl2, bl3);
                mma16816(sacc[2 * nb4],     aq, bh0, bh1);
                mma16816(sacc[2 * nb4 + 1], aq, bh2, bh3);
                mma16816(sacc[2 * nb4],     al, bh0, bh1);
                mma16816(sacc[2 * nb4 + 1], al, bh2, bh3);
                mma16816(sacc[2 * nb4],     aq, bl0, bl1);
                mma16816(sacc[2 * nb4 + 1], aq, bl2, bl3);
            }
        }

        uint32_t pf[4][4];
        #pragma unroll
        for (int nb = 0; nb < 8; nb++) {
            float e0 = ex2f(sacc[nb][0]);
            float e1 = ex2f(sacc[nb][1]);
            float e2 = ex2f(sacc[nb][2]);
            float e3 = ex2f(sacc[nb][3]);
            den0 += e0 + e1;
            den1 += e2 + e3;
            int kkj = nb >> 1, half = (nb & 1) * 2;
            pf[kkj][half]     = packbf2(e0, e1);
            pf[kkj][half + 1] = packbf2(e2, e3);
        }

        #pragma unroll
        for (int kkj = 0; kkj < 4; kkj++) {
            #pragma unroll
            for (int cb = 0; cb < 8; cb++) {
                uint32_t bh0, bh1, bh2, bh3;
                ldsm4(gB + (uint32_t)(cb * 16 * GSTR + kkj * 32), bh0, bh1, bh2, bh3);
                mma16816(oacc[2 * cb],     pf[kkj], bh0, bh1);
                mma16816(oacc[2 * cb + 1], pf[kkj], bh2, bh3);
            }
        }
        __syncthreads();
    }

    // ---- partial denominators + partial O (fp32) ----
    den0 += __shfl_xor_sync(0xFFFFFFFF, den0, 1);
    den0 += __shfl_xor_sync(0xFFFFFFFF, den0, 2);
    den1 += __shfl_xor_sync(0xFFFFFFFF, den1, 1);
    den1 += __shfl_xor_sync(0xFFFFFFFF, den1, 2);

    const int r0 = i0 + w * 16 + (lane >> 2);
    const size_t orow = (size_t)(ks * BATCH + bb) * NPIX + r0;
    float* dst = g_o + orow * CIDIM + (lane & 3) * 2;
    #pragma unroll
    for (int cb = 0; cb < 16; cb++) {
        *(float2*)(dst + cb * 8) = make_float2(oacc[cb][0], oacc[cb][1]);
        *(float2*)(dst + 8 * CIDIM + cb * 8) = make_float2(oacc[cb][2], oacc[cb][3]);
    }
    if ((lane & 3) == 0) {
        g_den[orow]     = den0;
        g_den[orow + 8] = den1;
    }
}

// ================= combine: y = (sum_s O_s) / (sum_s den_s), split hi/lo ====
#define ROWS_TOT (BATCH * NPIX)                 // 32768
#define F4_PER_SPLIT (ROWS_TOT * CIDIM / 4)     // 1048576

__global__ __launch_bounds__(256) void combine_kernel()
{
    int i = blockIdx.x * 256 + threadIdx.x;     // float4 index
    int row = i >> 5;
    float d = g_den[row] + g_den[row + ROWS_TOT]
            + g_den[row + 2 * ROWS_TOT] + g_den[row + 3 * ROWS_TOT];
    float inv = 1.0f / d;
    const float4* o4 = (const float4*)g_o;
    float4 a = o4[i];
    float4 b = o4[i + F4_PER_SPLIT];
    float4 c = o4[i + 2 * F4_PER_SPLIT];
    float4 e = o4[i + 3 * F4_PER_SPLIT];
    float v0 = (a.x + b.x + c.x + e.x) * inv;
    float v1 = (a.y + b.y + c.y + e.y) * inv;
    float v2 = (a.z + b.z + c.z + e.z) * inv;
    float v3 = (a.w + b.w + c.w + e.w) * inv;
    uint32_t h01, l01, h23, l23;
    split2(v0, v1, h01, l01);
    split2(v2, v3, h23, l23);
    ((uint2*)g_y_h)[i] = make_uint2(h01, h23);
    ((uint2*)g_y_l)[i] = make_uint2(l01, l23);
}

// ================= HMMA outproj: out = W_w @ y + b + x =================
#define OP_STR 272
#define OP_WH 0
#define OP_WL 34816
#define OP_YH 69632
#define OP_YL 104448
#define OP_SMEM 139264

__global__ __launch_bounds__(256, 1) void outproj_kernel(
    const float* __restrict__ Wb, const float* __restrict__ x,
    float* __restrict__ out)
{
    extern __shared__ char smem[];
    const uint32_t sb = smem_to_u32(smem);
    const int tid = threadIdx.x;
    const int w = tid >> 5, lane = tid & 31;
    const int wm = w & 3, wn = w >> 2;
    const int pt = blockIdx.x;
    const int c0 = blockIdx.y * 128;
    const int bb = pt >> 5;
    const int n0 = (pt & 31) * 128;

    const __nv_bfloat16* wwh = g_wsp_h + 3 * 32768;
    const __nv_bfloat16* wwl = g_wsp_l + 3 * 32768;
    const __nv_bfloat16* yh = g_y_h + ((size_t)bb * NPIX + n0) * CIDIM;
    const __nv_bfloat16* yl = g_y_l + ((size_t)bb * NPIX + n0) * CIDIM;

    #pragma unroll
    for (int t = 0; t < 8; t++) {
        int q = tid + t * 256;
        int r = q >> 4, j = q & 15;
        uint32_t d = sb + OP_WH + r * OP_STR + j * 16;
        size_t g = (size_t)(c0 + r) * CIDIM + j * 8;
        cp16(d, wwh + g);
        cp16(d + (OP_WL - OP_WH), wwl + g);
    }
    #pragma unroll
    for (int t = 0; t < 8; t++) {
        int q = tid + t * 256;
        int r = q >> 4, j = q & 15;
        uint32_t d = sb + OP_YH + r * OP_STR + j * 16;
        size_t g = (size_t)r * CIDIM + j * 8;
        cp16(d, yh + g);
        cp16(d + (OP_YL - OP_YH), yl + g);
    }
    CP_COMMIT();
    CP_WAIT0();
    __syncthreads();

    const uint32_t a_base = sb + OP_WH +
        (uint32_t)((wm * 32 + (lane & 15)) * OP_STR + (lane >> 4) * 16);
    const uint32_t b_base = sb + OP_YH +
        (uint32_t)((wn * 64 + (lane & 7) + ((lane >> 4) & 1) * 8) * OP_STR
                   + ((lane >> 3) & 1) * 16);

    float acc[2][8][4];
    #pragma unroll
    for (int i = 0; i < 2; i++)
        #pragma unroll
        for (int j = 0; j < 8; j++)
            #pragma unroll
            for (int q = 0; q < 4; q++) acc[i][j][q] = 0.f;

    #pragma unroll
    for (int kk = 0; kk < 8; kk++) {
        uint32_t aH[2][4], aL[2][4];
        #pragma unroll
        for (int m = 0; m < 2; m++) {
            uint32_t aa = a_base + kk * 32 + m * 16 * OP_STR;
            ldsm4(aa,                  aH[m][0], aH[m][1], aH[m][2], aH[m][3]);
            ldsm4(aa + (OP_WL - OP_WH), aL[m][0], aL[m][1], aL[m][2], aL[m][3]);
        }
        #pragma unroll
        for (int ng = 0; ng < 4; ng++) {
            uint32_t bh0, bh1, bh2, bh3, bl0, bl1, bl2, bl3;
            uint32_t ba = b_base + kk * 32 + ng * 16 * OP_STR;
            ldsm4(ba,                  bh0, bh1, bh2, bh3);
            ldsm4(ba + (OP_YL - OP_YH), bl0, bl1, bl2, bl3);
            #pragma unroll
            for (int m = 0; m < 2; m++) {
                mma16816(acc[m][2 * ng],     aH[m], bh0, bh1);
                mma16816(acc[m][2 * ng + 1], aH[m], bh2, bh3);
                mma16816(acc[m][2 * ng],     aL[m], bh0, bh1);
                mma16816(acc[m][2 * ng + 1], aL[m], bh2, bh3);
                mma16816(acc[m][2 * ng],     aH[m], bl0, bl1);
                mma16816(acc[m][2 * ng + 1], aH[m], bl2, bl3);
            }
        }
    }

    const int c_row = c0 + wm * 32 + (lane >> 2);
    const int p_col = wn * 64 + (lane & 3) * 2;
    #pragma unroll
    for (int m = 0; m < 2; m++) {
        int c = c_row + m * 16;
        float b0 = Wb[c], b1 = Wb[c + 8];
        #pragma unroll
        for (int n8 = 0; n8 < 8; n8++) {
            size_t a0 = ((size_t)bb * CDIM + c) * NPIX + n0 + p_col + n8 * 8;
            float2 xv = *(const float2*)&x[a0];
            *(float2*)&out[a0] = make_float2(acc[m][n8][0] + b0 + xv.x,
                                             acc[m][n8][1] + b0 + xv.y);
            size_t a1 = a0 + (size_t)8 * NPIX;
            float2 xv1 = *(const float2*)&x[a1];
            *(float2*)&out[a1] = make_float2(acc[m][n8][2] + b1 + xv1.x,
                                             acc[m][n8][3] + b1 + xv1.y);
        }
    }
}

extern "C" void kernel_launch(void* const* d_in, const int* in_sizes, int n_in,
                              void* d_out, int out_size) {
    const float* x    = (const float*)d_in[0];
    const float* g_w  = (const float*)d_in[1];
    const float* g_b  = (const float*)d_in[2];
    const float* th_w = (const float*)d_in[3];
    const float* th_b = (const float*)d_in[4];
    const float* ph_w = (const float*)d_in[5];
    const float* ph_b = (const float*)d_in[6];
    const float* W_w  = (const float*)d_in[7];
    const float* W_b  = (const float*)d_in[8];
    float* out = (float*)d_out;

    cudaFuncSetAttribute(proj_kernel,
                         cudaFuncAttributeMaxDynamicSharedMemorySize, PROJ_SMEM);
    cudaFuncSetAttribute(attn_kernel,
                         cudaFuncAttributeMaxDynamicSharedMemorySize, ATTN_SMEM);
    cudaFuncSetAttribute(outproj_kernel,
                         cudaFuncAttributeMaxDynamicSharedMemorySize, OP_SMEM);

    xsplit_kernel<<<BATCH * CDIM * NPIX / 4 / 256, 256>>>(x);
    wsplit_kernel<<<4 * 32768 / 256, 256>>>(th_w, ph_w, g_w, W_w);
    proj_kernel<<<dim3(BATCH * NPIX / 128, 3), 256, PROJ_SMEM>>>(th_b, ph_b, g_b);
    attn_kernel<<<dim3(NPIX / QT, BATCH, KSPLIT), 256, ATTN_SMEM>>>();
    combine_kernel<<<F4_PER_SPLIT / 256, 256>>>();
    outproj_kernel<<<dim3(BATCH * NPIX / 128, CDIM / 128), 256, OP_SMEM>>>(W_b, x, out);
}

// round 14
// speedup vs baseline: 1.4675x; 1.3621x over previous
#include <cuda_runtime.h>
#include <cuda_bf16.h>
#include <cuda_fp16.h>
#include <cstdint>
#include <cstddef>

#define BATCH 8
#define CDIM 256
#define CIDIM 128
#define NPIX 4096
#define QT 128
#define JT 64
#define KSPLIT 8
#define NSPL (NPIX / KSPLIT)          // 512 keys per split
#define NJT_PER (NSPL / JT)           // 8 j-tiles per CTA
#define L2E 1.4426950408889634f

// ---------------- scratch (__device__ globals; no allocation) ----------------
static __device__ __nv_bfloat16 g_x_h [BATCH * CDIM * NPIX];
static __device__ __nv_bfloat16 g_x_l [BATCH * CDIM * NPIX];
static __device__ __nv_bfloat16 g_wsp_h[4 * 32768];
static __device__ __nv_bfloat16 g_wsp_l[4 * 32768];
static __device__ __half        g_th  [BATCH * NPIX * CIDIM];  // fp16, pre-scaled log2e
static __device__ __half        g_ph  [BATCH * NPIX * CIDIM];  // fp16
static __device__ __nv_bfloat16 g_gm_h[BATCH * CIDIM * NPIX];  // bf16 (PV operand)
static __device__ __nv_bfloat16 g_y_h [BATCH * NPIX * CIDIM];
static __device__ __nv_bfloat16 g_y_l [BATCH * NPIX * CIDIM];
static __device__ float g_o  [KSPLIT * BATCH * NPIX * CIDIM];  // partial O
static __device__ float g_den[KSPLIT * BATCH * NPIX];          // partial den

// ---------------- PTX helpers ----------------
__device__ __forceinline__ uint32_t smem_to_u32(const void* p) {
    uint32_t a;
    asm("{ .reg .u64 t; cvta.to.shared.u64 t, %1; cvt.u32.u64 %0, t; }"
        : "=r"(a) : "l"(p));
    return a;
}
__device__ __forceinline__ void cp16(uint32_t dst, const void* src) {
    asm volatile("cp.async.cg.shared.global [%0], [%1], 16;" :: "r"(dst), "l"(src) : "memory");
}
#define CP_COMMIT() asm volatile("cp.async.commit_group;" ::: "memory")
#define CP_WAIT0()  asm volatile("cp.async.wait_group 0;" ::: "memory")
#define CP_WAIT1()  asm volatile("cp.async.wait_group 1;" ::: "memory")

__device__ __forceinline__ void ldsm4(uint32_t a, uint32_t& r0, uint32_t& r1,
                                      uint32_t& r2, uint32_t& r3) {
    asm volatile("ldmatrix.sync.aligned.m8n8.x4.shared.b16 {%0,%1,%2,%3}, [%4];"
                 : "=r"(r0), "=r"(r1), "=r"(r2), "=r"(r3) : "r"(a));
}
__device__ __forceinline__ void ldsm4t(uint32_t a, uint32_t& r0, uint32_t& r1,
                                       uint32_t& r2, uint32_t& r3) {
    asm volatile("ldmatrix.sync.aligned.m8n8.x4.trans.shared.b16 {%0,%1,%2,%3}, [%4];"
                 : "=r"(r0), "=r"(r1), "=r"(r2), "=r"(r3) : "r"(a));
}
// bf16 MMA (PV + projection kernels)
__device__ __forceinline__ void mma16816(float* d, const uint32_t* a,
                                         uint32_t b0, uint32_t b1) {
    asm volatile("mma.sync.aligned.m16n8k16.row.col.f32.bf16.bf16.f32 "
                 "{%0,%1,%2,%3}, {%4,%5,%6,%7}, {%8,%9}, {%0,%1,%2,%3};"
                 : "+f"(d[0]), "+f"(d[1]), "+f"(d[2]), "+f"(d[3])
                 : "r"(a[0]), "r"(a[1]), "r"(a[2]), "r"(a[3]), "r"(b0), "r"(b1));
}
// fp16 MMA (S phase)
__device__ __forceinline__ void mma16816f(float* d, const uint32_t* a,
                                          uint32_t b0, uint32_t b1) {
    asm volatile("mma.sync.aligned.m16n8k16.row.col.f32.f16.f16.f32 "
                 "{%0,%1,%2,%3}, {%4,%5,%6,%7}, {%8,%9}, {%0,%1,%2,%3};"
                 : "+f"(d[0]), "+f"(d[1]), "+f"(d[2]), "+f"(d[3])
                 : "r"(a[0]), "r"(a[1]), "r"(a[2]), "r"(a[3]), "r"(b0), "r"(b1));
}
__device__ __forceinline__ uint32_t packbf2(float lo, float hi) {
    uint32_t r;
    asm("cvt.rn.satfinite.bf16x2.f32 %0, %1, %2;" : "=r"(r) : "f"(hi), "f"(lo));
    return r;
}
__device__ __forceinline__ uint32_t packh2(float lo, float hi) {
    uint32_t r;
    asm("cvt.rn.f16x2.f32 %0, %1, %2;" : "=r"(r) : "f"(hi), "f"(lo));
    return r;
}
__device__ __forceinline__ float ex2f(float x) {
    float r;
    asm("ex2.approx.f32 %0, %1;" : "=f"(r) : "f"(x));
    return r;
}
__device__ __forceinline__ void split2(float v0, float v1, uint32_t& h, uint32_t& l) {
    __nv_bfloat16 h0 = __float2bfloat16(v0), h1 = __float2bfloat16(v1);
    float f0 = __bfloat162float(h0), f1 = __bfloat162float(h1);
    __nv_bfloat162 hh; hh.x = h0; hh.y = h1;
    __nv_bfloat162 ll; ll.x = __float2bfloat16(v0 - f0); ll.y = __float2bfloat16(v1 - f1);
    h = *(uint32_t*)&hh;
    l = *(uint32_t*)&ll;
}

// ================= convert kernels =================
__global__ __launch_bounds__(256) void xsplit_kernel(const float* __restrict__ x) {
    int i = blockIdx.x * 256 + threadIdx.x;
    float4 v = ((const float4*)x)[i];
    uint32_t h01, l01, h23, l23;
    split2(v.x, v.y, h01, l01);
    split2(v.z, v.w, h23, l23);
    ((uint2*)g_x_h)[i] = make_uint2(h01, h23);
    ((uint2*)g_x_l)[i] = make_uint2(l01, l23);
}
__global__ __launch_bounds__(256) void wsplit_kernel(
    const float* __restrict__ thw, const float* __restrict__ phw,
    const float* __restrict__ gw,  const float* __restrict__ Ww) {
    int idx = blockIdx.x * 256 + threadIdx.x;
    int seg = idx >> 15, loc = idx & 32767;
    const float* src = (seg == 0) ? thw : (seg == 1) ? phw : (seg == 2) ? gw : Ww;
    float v = src[loc];
    __nv_bfloat16 h = __float2bfloat16(v);
    g_wsp_h[idx] = h;
    g_wsp_l[idx] = __float2bfloat16(v - __bfloat162float(h));
}

// ================= HMMA projection (3-pass bf16; fp16/bf16 epilogues) =======
#define PJ_XSTR 272
#define PJ_WSTR 144
#define PJ_XH 0
#define PJ_XL 17408
#define PJ_WH 34816
#define PJ_WL 53248
#define PJ_STAGE 71680
#define PROJ_SMEM (2 * PJ_STAGE)

__global__ __launch_bounds__(256, 1) void proj_kernel(
    const float* __restrict__ th_b, const float* __restrict__ ph_b,
    const float* __restrict__ g_b)
{
    extern __shared__ char smem[];
    const uint32_t sb = smem_to_u32(smem);
    const int tid = threadIdx.x;
    const int w = tid >> 5, lane = tid & 31;
    const int wm = w & 3, wn = w >> 2;
    const int flavor = blockIdx.y;
    const int pt = blockIdx.x;
    const int bb = pt >> 5;
    const int n0 = (pt & 31) * 128;

    const __nv_bfloat16* xh = g_x_h + (size_t)bb * CDIM * NPIX + n0;
    const __nv_bfloat16* xl = g_x_l + (size_t)bb * CDIM * NPIX + n0;
    const __nv_bfloat16* wh = g_wsp_h + flavor * 32768;
    const __nv_bfloat16* wl = g_wsp_l + flavor * 32768;

    auto load_chunk = [&](int s, int k0) {
        uint32_t base = sb + s * PJ_STAGE;
        #pragma unroll
        for (int t = 0; t < 4; t++) {
            int q = tid + t * 256;
            int k = q >> 4, j = q & 15;
            uint32_t d = base + PJ_XH + k * PJ_XSTR + j * 16;
            size_t g = (size_t)(k0 + k) * NPIX + j * 8;
            cp16(d, xh + g);
            cp16(d + (PJ_XL - PJ_XH), xl + g);
        }
        #pragma unroll
        for (int t = 0; t < 4; t++) {
            int q = tid + t * 256;
            int o = q >> 3, j = q & 7;
            uint32_t d = base + PJ_WH + o * PJ_WSTR + j * 16;
            size_t g = (size_t)o * CDIM + k0 + j * 8;
            cp16(d, wh + g);
            cp16(d + (PJ_WL - PJ_WH), wl + g);
        }
    };
    load_chunk(0, 0);
    CP_COMMIT();

    uint32_t a_base, b_base, a_m16, a_kk, b_ng, b_kk, a_lo, b_lo;
    if (flavor < 2) {
        a_base = PJ_XH + (uint32_t)(((lane & 7) + ((lane >> 4) & 1) * 8) * PJ_XSTR
                                    + wm * 64 + ((lane >> 3) & 1) * 16);
        a_m16 = 32;               a_kk = 16 * PJ_XSTR;  a_lo = PJ_XL - PJ_XH;
        b_base = PJ_WH + (uint32_t)((wn * 64 + (lane & 7) + ((lane >> 4) & 1) * 8) * PJ_WSTR
                                    + ((lane >> 3) & 1) * 16);
        b_ng = 16 * PJ_WSTR;      b_kk = 32;            b_lo = PJ_WL - PJ_WH;
    } else {
        a_base = PJ_WH + (uint32_t)((wm * 32 + (lane & 15)) * PJ_WSTR + (lane >> 4) * 16);
        a_m16 = 16 * PJ_WSTR;     a_kk = 32;            a_lo = PJ_WL - PJ_WH;
        b_base = PJ_XH + (uint32_t)(((lane & 7) + ((lane >> 3) & 1) * 8) * PJ_XSTR
                                    + wn * 128 + (lane >> 4) * 16);
        b_ng = 32;                b_kk = 16 * PJ_XSTR;  b_lo = PJ_XL - PJ_XH;
    }

    float acc[2][8][4];
    #pragma unroll
    for (int i = 0; i < 2; i++)
        #pragma unroll
        for (int j = 0; j < 8; j++)
            #pragma unroll
            for (int q = 0; q < 4; q++) acc[i][j][q] = 0.f;

    #pragma unroll 1
    for (int ch = 0; ch < 4; ch++) {
        if (ch < 3) load_chunk((ch + 1) & 1, (ch + 1) * 64);
        CP_COMMIT();
        CP_WAIT1();
        __syncthreads();
        const uint32_t stb = sb + (ch & 1) * PJ_STAGE;
        #pragma unroll
        for (int kk = 0; kk < 4; kk++) {
            uint32_t aH[2][4], aL[2][4];
            #pragma unroll
            for (int m = 0; m < 2; m++) {
                uint32_t aa = stb + a_base + kk * a_kk + m * a_m16;
                if (flavor < 2) {
                    ldsm4t(aa,        aH[m][0], aH[m][1], aH[m][2], aH[m][3]);
                    ldsm4t(aa + a_lo, aL[m][0], aL[m][1], aL[m][2], aL[m][3]);
                } else {
                    ldsm4(aa,         aH[m][0], aH[m][1], aH[m][2], aH[m][3]);
                    ldsm4(aa + a_lo,  aL[m][0], aL[m][1], aL[m][2], aL[m][3]);
                }
            }
            #pragma unroll
            for (int ng = 0; ng < 4; ng++) {
                uint32_t bh0, bh1, bh2, bh3, bl0, bl1, bl2, bl3;
                uint32_t ba = stb + b_base + kk * b_kk + ng * b_ng;
                if (flavor < 2) {
                    ldsm4(ba,         bh0, bh1, bh2, bh3);
                    ldsm4(ba + b_lo,  bl0, bl1, bl2, bl3);
                } else {
                    ldsm4t(ba,        bh0, bh1, bh2, bh3);
                    ldsm4t(ba + b_lo, bl0, bl1, bl2, bl3);
                }
                #pragma unroll
                for (int m = 0; m < 2; m++) {
                    mma16816(acc[m][2 * ng],     aH[m], bh0, bh1);
                    mma16816(acc[m][2 * ng + 1], aH[m], bh2, bh3);
                    mma16816(acc[m][2 * ng],     aL[m], bh0, bh1);
                    mma16816(acc[m][2 * ng + 1], aL[m], bh2, bh3);
                    mma16816(acc[m][2 * ng],     aH[m], bl0, bl1);
                    mma16816(acc[m][2 * ng + 1], aH[m], bl2, bl3);
                }
            }
        }
        __syncthreads();
    }

    if (flavor < 2) {
        __half* dst = (flavor == 0) ? g_th : g_ph;
        const float* bias = (flavor == 0) ? th_b : ph_b;
        const float scl = (flavor == 0) ? L2E : 1.0f;
        const int m_row = wm * 32 + (lane >> 2);
        const int o_col = wn * 64 + (lane & 3) * 2;
        #pragma unroll
        for (int m = 0; m < 2; m++) {
            #pragma unroll
            for (int n8 = 0; n8 < 8; n8++) {
                float2 bv = *(const float2*)&bias[o_col + n8 * 8];
                int pix = n0 + m_row + m * 16;
                size_t a0 = ((size_t)bb * NPIX + pix) * CIDIM + o_col + n8 * 8;
                *(uint32_t*)&dst[a0] =
                    packh2((acc[m][n8][0] + bv.x) * scl, (acc[m][n8][1] + bv.y) * scl);
                size_t a1 = a0 + (size_t)8 * CIDIM;
                *(uint32_t*)&dst[a1] =
                    packh2((acc[m][n8][2] + bv.x) * scl, (acc[m][n8][3] + bv.y) * scl);
            }
        }
    } else {
        const int o_row = wm * 32 + (lane >> 2);
        const int p_col = wn * 64 + (lane & 3) * 2;
        #pragma unroll
        for (int m = 0; m < 2; m++) {
            int o = o_row + m * 16;
            float b0 = g_b[o], b1 = g_b[o + 8];
            #pragma unroll
            for (int n8 = 0; n8 < 8; n8++) {
                size_t a0 = ((size_t)bb * CIDIM + o) * NPIX + n0 + p_col + n8 * 8;
                *(uint32_t*)&g_gm_h[a0] =
                    packbf2(acc[m][n8][0] + b0, acc[m][n8][1] + b0);
                size_t a1 = a0 + (size_t)8 * NPIX;
                *(uint32_t*)&g_gm_h[a1] =
                    packbf2(acc[m][n8][2] + b1, acc[m][n8][3] + b1);
            }
        }
    }
}

// ================= HMMA flash attention (fp16 S single-pass, 2 CTAs/SM) =====
#define QSTR 272
#define GSTR 144
#define OFF_Q 0
#define OFF_ST0 34816
#define ST_K 0
#define ST_G 17408
#define STAGE_SZ 35840
#define ATTN_SMEM (OFF_ST0 + 2 * STAGE_SZ)   // 106496 -> 2 CTAs/SM

__global__ __launch_bounds__(256, 2) void attn_kernel()
{
    extern __shared__ char smem[];
    const uint32_t sb = smem_to_u32(smem);
    const int tid = threadIdx.x;
    const int w = tid >> 5, lane = tid & 31;
    const int bb = blockIdx.y;
    const int i0 = blockIdx.x * QT;
    const int ks = blockIdx.z;
    const int jbase = ks * NSPL;

    const __half* qp = g_th + ((size_t)bb * NPIX + i0) * CIDIM;
    const __half* phb = g_ph + (size_t)bb * NPIX * CIDIM;
    const __nv_bfloat16* ghb = g_gm_h + (size_t)bb * CIDIM * NPIX;

    // Q fp16: 128 rows x 256B
    #pragma unroll
    for (int t = 0; t < 8; t++) {
        int q = tid + t * 256;
        int r = q >> 4, c = q & 15;
        cp16(sb + OFF_Q + r * QSTR + c * 16, qp + r * CIDIM + c * 8);
    }

    auto load_stage = [&](int s, int j0) {
        uint32_t base = sb + OFF_ST0 + s * STAGE_SZ;
        #pragma unroll
        for (int t = 0; t < 4; t++) {           // K fp16: 64 rows x 256B
            int q = tid + t * 256;
            int j = q >> 4, c = q & 15;
            cp16(base + ST_K + j * QSTR + c * 16,
                 phb + (size_t)(j0 + j) * CIDIM + c * 8);
        }
        #pragma unroll
        for (int t = 0; t < 4; t++) {           // G bf16: 128 rows x 128B
            int q = tid + t * 256;
            int c = q >> 3, jc = q & 7;
            cp16(base + ST_G + c * GSTR + jc * 16,
                 ghb + (size_t)c * NPIX + j0 + jc * 8);
        }
    };
    load_stage(0, jbase);
    CP_COMMIT();

    const uint32_t aq_base = sb + OFF_Q +
        (uint32_t)((w * 16 + (lane & 15)) * QSTR + (lane >> 4) * 16);
    const int b_row  = (lane & 7) + ((lane >> 4) & 1) * 8;
    const int b_byte = ((lane >> 3) & 1) * 16;

    float oacc[16][4];
    #pragma unroll
    for (int i = 0; i < 16; i++)
        #pragma unroll
        for (int j = 0; j < 4; j++) oacc[i][j] = 0.f;
    float den0 = 0.f, den1 = 0.f;

    #pragma unroll 1
    for (int jt = 0; jt < NJT_PER; jt++) {
        const int s = jt & 1;
        if (jt + 1 < NJT_PER) load_stage(s ^ 1, jbase + (jt + 1) * JT);
        CP_COMMIT();
        CP_WAIT1();
        __syncthreads();

        const uint32_t stb = sb + OFF_ST0 + s * STAGE_SZ;
        const uint32_t kB = stb + ST_K + (uint32_t)(b_row * QSTR + b_byte);
        const uint32_t gB = stb + ST_G + (uint32_t)(b_row * GSTR + b_byte);

        #pragma unroll
        for (int h = 0; h < 2; h++) {           // two 32-key halves
            float sacc[4][4];
            #pragma unroll
            for (int i = 0; i < 4; i++)
                #pragma unroll
                for (int j = 0; j < 4; j++) sacc[i][j] = 0.f;

            #pragma unroll
            for (int kk = 0; kk < 8; kk++) {
                uint32_t a[4];
                ldsm4(aq_base + kk * 32, a[0], a[1], a[2], a[3]);
                #pragma unroll
                for (int nb = 0; nb < 2; nb++) {
                    uint32_t b0, b1, b2, b3;
                    ldsm4(kB + (uint32_t)((h * 2 + nb) * 16 * QSTR + kk * 32),
                          b0, b1, b2, b3);
                    mma16816f(sacc[2 * nb],     a, b0, b1);
                    mma16816f(sacc[2 * nb + 1], a, b2, b3);
                }
            }

            uint32_t pf[2][4];
            #pragma unroll
            for (int nb = 0; nb < 4; nb++) {
                float e0 = ex2f(sacc[nb][0]);
                float e1 = ex2f(sacc[nb][1]);
                float e2 = ex2f(sacc[nb][2]);
                float e3 = ex2f(sacc[nb][3]);
                den0 += e0 + e1;
                den1 += e2 + e3;
                int kkj = nb >> 1, hf = (nb & 1) * 2;
                pf[kkj][hf]     = packbf2(e0, e1);
                pf[kkj][hf + 1] = packbf2(e2, e3);
            }

            #pragma unroll
            for (int kkj = 0; kkj < 2; kkj++) {
                #pragma unroll
                for (int cb = 0; cb < 8; cb++) {
                    uint32_t b0, b1, b2, b3;
                    ldsm4(gB + (uint32_t)(cb * 16 * GSTR + (h * 2 + kkj) * 32),
                          b0, b1, b2, b3);
                    mma16816(oacc[2 * cb],     pf[kkj], b0, b1);
                    mma16816(oacc[2 * cb + 1], pf[kkj], b2, b3);
                }
            }
        }
        __syncthreads();
    }

    den0 += __shfl_xor_sync(0xFFFFFFFF, den0, 1);
    den0 += __shfl_xor_sync(0xFFFFFFFF, den0, 2);
    den1 += __shfl_xor_sync(0xFFFFFFFF, den1, 1);
    den1 += __shfl_xor_sync(0xFFFFFFFF, den1, 2);

    const int r0 = i0 + w * 16 + (lane >> 2);
    const size_t orow = (size_t)(ks * BATCH + bb) * NPIX + r0;
    float* dst = g_o + orow * CIDIM + (lane & 3) * 2;
    #pragma unroll
    for (int cb = 0; cb < 16; cb++) {
        *(float2*)(dst + cb * 8) = make_float2(oacc[cb][0], oacc[cb][1]);
        *(float2*)(dst + 8 * CIDIM + cb * 8) = make_float2(oacc[cb][2], oacc[cb][3]);
    }
    if ((lane & 3) == 0) {
        g_den[orow]     = den0;
        g_den[orow + 8] = den1;
    }
}

// ================= combine: y = (sum_s O_s) / (sum_s den_s) ====
#define ROWS_TOT (BATCH * NPIX)                 // 32768
#define F4_PER_SPLIT (ROWS_TOT * CIDIM / 4)     // 1048576

__global__ __launch_bounds__(256) void combine_kernel()
{
    int i = blockIdx.x * 256 + threadIdx.x;
    int row = i >> 5;
    float d = 0.f;
    #pragma unroll
    for (int s = 0; s < KSPLIT; s++) d += g_den[row + s * ROWS_TOT];
    float inv = 1.0f / d;
    const float4* o4 = (const float4*)g_o;
    float v0 = 0.f, v1 = 0.f, v2 = 0.f, v3 = 0.f;
    #pragma unroll
    for (int s = 0; s < KSPLIT; s++) {
        float4 a = o4[i + s * F4_PER_SPLIT];
        v0 += a.x; v1 += a.y; v2 += a.z; v3 += a.w;
    }
    v0 *= inv; v1 *= inv; v2 *= inv; v3 *= inv;
    uint32_t h01, l01, h23, l23;
    split2(v0, v1, h01, l01);
    split2(v2, v3, h23, l23);
    ((uint2*)g_y_h)[i] = make_uint2(h01, h23);
    ((uint2*)g_y_l)[i] = make_uint2(l01, l23);
}

// ================= HMMA outproj: out = W_w @ y + b + x =================
#define OP_STR 272
#define OP_WH 0
#define OP_WL 34816
#define OP_YH 69632
#define OP_YL 104448
#define OP_SMEM 139264

__global__ __launch_bounds__(256, 1) void outproj_kernel(
    const float* __restrict__ Wb, const float* __restrict__ x,
    float* __restrict__ out)
{
    extern __shared__ char smem[];
    const uint32_t sb = smem_to_u32(smem);
    const int tid = threadIdx.x;
    const int w = tid >> 5, lane = tid & 31;
    const int wm = w & 3, wn = w >> 2;
    const int pt = blockIdx.x;
    const int c0 = blockIdx.y * 128;
    const int bb = pt >> 5;
    const int n0 = (pt & 31) * 128;

    const __nv_bfloat16* wwh = g_wsp_h + 3 * 32768;
    const __nv_bfloat16* wwl = g_wsp_l + 3 * 32768;
    const __nv_bfloat16* yh = g_y_h + ((size_t)bb * NPIX + n0) * CIDIM;
    const __nv_bfloat16* yl = g_y_l + ((size_t)bb * NPIX + n0) * CIDIM;

    #pragma unroll
    for (int t = 0; t < 8; t++) {
        int q = tid + t * 256;
        int r = q >> 4, j = q & 15;
        uint32_t d = sb + OP_WH + r * OP_STR + j * 16;
        size_t g = (size_t)(c0 + r) * CIDIM + j * 8;
        cp16(d, wwh + g);
        cp16(d + (OP_WL - OP_WH), wwl + g);
    }
    #pragma unroll
    for (int t = 0; t < 8; t++) {
        int q = tid + t * 256;
        int r = q >> 4, j = q & 15;
        uint32_t d = sb + OP_YH + r * OP_STR + j * 16;
        size_t g = (size_t)r * CIDIM + j * 8;
        cp16(d, yh + g);
        cp16(d + (OP_YL - OP_YH), yl + g);
    }
    CP_COMMIT();
    CP_WAIT0();
    __syncthreads();

    const uint32_t a_base = sb + OP_WH +
        (uint32_t)((wm * 32 + (lane & 15)) * OP_STR + (lane >> 4) * 16);
    const uint32_t b_base = sb + OP_YH +
        (uint32_t)((wn * 64 + (lane & 7) + ((lane >> 4) & 1) * 8) * OP_STR
                   + ((lane >> 3) & 1) * 16);

    float acc[2][8][4];
    #pragma unroll
    for (int i = 0; i < 2; i++)
        #pragma unroll
        for (int j = 0; j < 8; j++)
            #pragma unroll
            for (int q = 0; q < 4; q++) acc[i][j][q] = 0.f;

    #pragma unroll
    for (int kk = 0; kk < 8; kk++) {
        uint32_t aH[2][4], aL[2][4];
        #pragma unroll
        for (int m = 0; m < 2; m++) {
            uint32_t aa = a_base + kk * 32 + m * 16 * OP_STR;
            ldsm4(aa,                  aH[m][0], aH[m][1], aH[m][2], aH[m][3]);
            ldsm4(aa + (OP_WL - OP_WH), aL[m][0], aL[m][1], aL[m][2], aL[m][3]);
        }
        #pragma unroll
        for (int ng = 0; ng < 4; ng++) {
            uint32_t bh0, bh1, bh2, bh3, bl0, bl1, bl2, bl3;
            uint32_t ba = b_base + kk * 32 + ng * 16 * OP_STR;
            ldsm4(ba,                  bh0, bh1, bh2, bh3);
            ldsm4(ba + (OP_YL - OP_YH), bl0, bl1, bl2, bl3);
            #pragma unroll
            for (int m = 0; m < 2; m++) {
                mma16816(acc[m][2 * ng],     aH[m], bh0, bh1);
                mma16816(acc[m][2 * ng + 1], aH[m], bh2, bh3);
                mma16816(acc[m][2 * ng],     aL[m], bh0, bh1);
                mma16816(acc[m][2 * ng + 1], aL[m], bh2, bh3);
                mma16816(acc[m][2 * ng],     aH[m], bl0, bl1);
                mma16816(acc[m][2 * ng + 1], aH[m], bl2, bl3);
            }
        }
    }

    const int c_row = c0 + wm * 32 + (lane >> 2);
    const int p_col = wn * 64 + (lane & 3) * 2;
    #pragma unroll
    for (int m = 0; m < 2; m++) {
        int c = c_row + m * 16;
        float b0 = Wb[c], b1 = Wb[c + 8];
        #pragma unroll
        for (int n8 = 0; n8 < 8; n8++) {
            size_t a0 = ((size_t)bb * CDIM + c) * NPIX + n0 + p_col + n8 * 8;
            float2 xv = *(const float2*)&x[a0];
            *(float2*)&out[a0] = make_float2(acc[m][n8][0] + b0 + xv.x,
                                             acc[m][n8][1] + b0 + xv.y);
            size_t a1 = a0 + (size_t)8 * NPIX;
            float2 xv1 = *(const float2*)&x[a1];
            *(float2*)&out[a1] = make_float2(acc[m][n8][2] + b1 + xv1.x,
                                             acc[m][n8][3] + b1 + xv1.y);
        }
    }
}

extern "C" void kernel_launch(void* const* d_in, const int* in_sizes, int n_in,
                              void* d_out, int out_size) {
    const float* x    = (const float*)d_in[0];
    const float* g_w  = (const float*)d_in[1];
    const float* g_b  = (const float*)d_in[2];
    const float* th_w = (const float*)d_in[3];
    const float* th_b = (const float*)d_in[4];
    const float* ph_w = (const float*)d_in[5];
    const float* ph_b = (const float*)d_in[6];
    const float* W_w  = (const float*)d_in[7];
    const float* W_b  = (const float*)d_in[8];
    float* out = (float*)d_out;

    cudaFuncSetAttribute(proj_kernel,
                         cudaFuncAttributeMaxDynamicSharedMemorySize, PROJ_SMEM);
    cudaFuncSetAttribute(attn_kernel,
                         cudaFuncAttributeMaxDynamicSharedMemorySize, ATTN_SMEM);
    cudaFuncSetAttribute(outproj_kernel,
                         cudaFuncAttributeMaxDynamicSharedMemorySize, OP_SMEM);

    xsplit_kernel<<<BATCH * CDIM * NPIX / 4 / 256, 256>>>(x);
    wsplit_kernel<<<4 * 32768 / 256, 256>>>(th_w, ph_w, g_w, W_w);
    proj_kernel<<<dim3(BATCH * NPIX / 128, 3), 256, PROJ_SMEM>>>(th_b, ph_b, g_b);
    attn_kernel<<<dim3(NPIX / QT, BATCH, KSPLIT), 256, ATTN_SMEM>>>();
    combine_kernel<<<F4_PER_SPLIT / 256, 256>>>();
    outproj_kernel<<<dim3(BATCH * NPIX / 128, CDIM / 128), 256, OP_SMEM>>>(W_b, x, out);
}

// round 15
// speedup vs baseline: 1.6186x; 1.1030x over previous
#include <cuda_runtime.h>
#include <cuda_bf16.h>
#include <cuda_fp16.h>
#include <cstdint>
#include <cstddef>

#define BATCH 8
#define CDIM 256
#define CIDIM 128
#define NPIX 4096
#define QT 128
#define JT 64
#define KSPLIT 8
#define NSPL (NPIX / KSPLIT)
#define NJT_PER (NSPL / JT)
#define L2E 1.4426950408889634f

// ---------------- scratch (__device__ globals; no allocation) ----------------
static __device__ __nv_bfloat16 g_x_h [BATCH * CDIM * NPIX];   // bf16 hi (g proj)
static __device__ __nv_bfloat16 g_x_l [BATCH * CDIM * NPIX];   // bf16 lo (g proj)
static __device__ __half        g_x_f [BATCH * CDIM * NPIX];   // fp16 (theta/phi proj)
static __device__ __nv_bfloat16 g_wsp_h[4 * 32768];            // g weights bf16 hi/lo
static __device__ __nv_bfloat16 g_wsp_l[4 * 32768];
static __device__ __half        g_wf  [3 * 32768];             // th, ph, W_w fp16
static __device__ __half        g_th  [BATCH * NPIX * CIDIM];  // fp16, pre-scaled log2e
static __device__ __half        g_ph  [BATCH * NPIX * CIDIM];
static __device__ __nv_bfloat16 g_gm_h[BATCH * CIDIM * NPIX];  // bf16 (PV operand)
static __device__ __half        g_y_f [BATCH * NPIX * CIDIM];  // fp16 y
static __device__ float g_o  [KSPLIT * BATCH * NPIX * CIDIM];
static __device__ float g_den[KSPLIT * BATCH * NPIX];

// ---------------- PTX helpers ----------------
__device__ __forceinline__ uint32_t smem_to_u32(const void* p) {
    uint32_t a;
    asm("{ .reg .u64 t; cvta.to.shared.u64 t, %1; cvt.u32.u64 %0, t; }"
        : "=r"(a) : "l"(p));
    return a;
}
__device__ __forceinline__ void cp16(uint32_t dst, const void* src) {
    asm volatile("cp.async.cg.shared.global [%0], [%1], 16;" :: "r"(dst), "l"(src) : "memory");
}
#define CP_COMMIT() asm volatile("cp.async.commit_group;" ::: "memory")
#define CP_WAIT0()  asm volatile("cp.async.wait_group 0;" ::: "memory")
#define CP_WAIT1()  asm volatile("cp.async.wait_group 1;" ::: "memory")

__device__ __forceinline__ void ldsm4(uint32_t a, uint32_t& r0, uint32_t& r1,
                                      uint32_t& r2, uint32_t& r3) {
    asm volatile("ldmatrix.sync.aligned.m8n8.x4.shared.b16 {%0,%1,%2,%3}, [%4];"
                 : "=r"(r0), "=r"(r1), "=r"(r2), "=r"(r3) : "r"(a));
}
__device__ __forceinline__ void ldsm4t(uint32_t a, uint32_t& r0, uint32_t& r1,
                                       uint32_t& r2, uint32_t& r3) {
    asm volatile("ldmatrix.sync.aligned.m8n8.x4.trans.shared.b16 {%0,%1,%2,%3}, [%4];"
                 : "=r"(r0), "=r"(r1), "=r"(r2), "=r"(r3) : "r"(a));
}
__device__ __forceinline__ void mma16816(float* d, const uint32_t* a,
                                         uint32_t b0, uint32_t b1) {
    asm volatile("mma.sync.aligned.m16n8k16.row.col.f32.bf16.bf16.f32 "
                 "{%0,%1,%2,%3}, {%4,%5,%6,%7}, {%8,%9}, {%0,%1,%2,%3};"
                 : "+f"(d[0]), "+f"(d[1]), "+f"(d[2]), "+f"(d[3])
                 : "r"(a[0]), "r"(a[1]), "r"(a[2]), "r"(a[3]), "r"(b0), "r"(b1));
}
__device__ __forceinline__ void mma16816f(float* d, const uint32_t* a,
                                          uint32_t b0, uint32_t b1) {
    asm volatile("mma.sync.aligned.m16n8k16.row.col.f32.f16.f16.f32 "
                 "{%0,%1,%2,%3}, {%4,%5,%6,%7}, {%8,%9}, {%0,%1,%2,%3};"
                 : "+f"(d[0]), "+f"(d[1]), "+f"(d[2]), "+f"(d[3])
                 : "r"(a[0]), "r"(a[1]), "r"(a[2]), "r"(a[3]), "r"(b0), "r"(b1));
}
__device__ __forceinline__ uint32_t packbf2(float lo, float hi) {
    uint32_t r;
    asm("cvt.rn.satfinite.bf16x2.f32 %0, %1, %2;" : "=r"(r) : "f"(hi), "f"(lo));
    return r;
}
__device__ __forceinline__ uint32_t packh2(float lo, float hi) {
    uint32_t r;
    asm("cvt.rn.f16x2.f32 %0, %1, %2;" : "=r"(r) : "f"(hi), "f"(lo));
    return r;
}
__device__ __forceinline__ float ex2f(float x) {
    float r;
    asm("ex2.approx.f32 %0, %1;" : "=f"(r) : "f"(x));
    return r;
}
__device__ __forceinline__ void split2(float v0, float v1, uint32_t& h, uint32_t& l) {
    __nv_bfloat16 h0 = __float2bfloat16(v0), h1 = __float2bfloat16(v1);
    float f0 = __bfloat162float(h0), f1 = __bfloat162float(h1);
    __nv_bfloat162 hh; hh.x = h0; hh.y = h1;
    __nv_bfloat162 ll; ll.x = __float2bfloat16(v0 - f0); ll.y = __float2bfloat16(v1 - f1);
    h = *(uint32_t*)&hh;
    l = *(uint32_t*)&ll;
}

// ================= convert kernels =================
__global__ __launch_bounds__(256) void xsplit_kernel(const float* __restrict__ x) {
    int i = blockIdx.x * 256 + threadIdx.x;
    float4 v = ((const float4*)x)[i];
    uint32_t h01, l01, h23, l23;
    split2(v.x, v.y, h01, l01);
    split2(v.z, v.w, h23, l23);
    ((uint2*)g_x_h)[i] = make_uint2(h01, h23);
    ((uint2*)g_x_l)[i] = make_uint2(l01, l23);
    ((uint2*)g_x_f)[i] = make_uint2(packh2(v.x, v.y), packh2(v.z, v.w));
}
__global__ __launch_bounds__(256) void wsplit_kernel(
    const float* __restrict__ thw, const float* __restrict__ phw,
    const float* __restrict__ gw,  const float* __restrict__ Ww) {
    int idx = blockIdx.x * 256 + threadIdx.x;
    int seg = idx >> 15, loc = idx & 32767;
    const float* src = (seg == 0) ? thw : (seg == 1) ? phw : (seg == 2) ? gw : Ww;
    float v = src[loc];
    if (seg == 2) {
        __nv_bfloat16 h = __float2bfloat16(v);
        g_wsp_h[idx] = h;
        g_wsp_l[idx] = __float2bfloat16(v - __bfloat162float(h));
    } else {
        int s = (seg == 3) ? 2 : seg;
        g_wf[s * 32768 + loc] = __float2half(v);
    }
}

// ================= theta/phi projection: fp16 single-pass ===================
// out[pix][ci] = x^T W^T ; A = x fp16 (trans), B = W fp16
#define QK_XSTR 272
#define QK_WSTR 144
#define QK_X 0
#define QK_W 17408
#define QK_STAGE 35840
#define QK_SMEM (2 * QK_STAGE)

__global__ __launch_bounds__(256, 1) void projqk_kernel(
    const float* __restrict__ th_b, const float* __restrict__ ph_b)
{
    extern __shared__ char smem[];
    const uint32_t sb = smem_to_u32(smem);
    const int tid = threadIdx.x;
    const int w = tid >> 5, lane = tid & 31;
    const int wm = w & 3, wn = w >> 2;
    const int flavor = blockIdx.y;
    const int pt = blockIdx.x;
    const int bb = pt >> 5;
    const int n0 = (pt & 31) * 128;

    const __half* xf = g_x_f + (size_t)bb * CDIM * NPIX + n0;
    const __half* wf = g_wf + flavor * 32768;

    auto load_chunk = [&](int s, int k0) {
        uint32_t base = sb + s * QK_STAGE;
        #pragma unroll
        for (int t = 0; t < 4; t++) {            // x: 64 k-rows x 256B
            int q = tid + t * 256;
            int k = q >> 4, j = q & 15;
            cp16(base + QK_X + k * QK_XSTR + j * 16,
                 xf + (size_t)(k0 + k) * NPIX + j * 8);
        }
        #pragma unroll
        for (int t = 0; t < 4; t++) {            // W: 128 o-rows x 128B
            int q = tid + t * 256;
            int o = q >> 3, j = q & 7;
            cp16(base + QK_W + o * QK_WSTR + j * 16,
                 wf + (size_t)o * CDIM + k0 + j * 8);
        }
    };
    load_chunk(0, 0);
    CP_COMMIT();

    const uint32_t a_base = QK_X +
        (uint32_t)(((lane & 7) + ((lane >> 4) & 1) * 8) * QK_XSTR
                   + wm * 64 + ((lane >> 3) & 1) * 16);
    const uint32_t b_base = QK_W +
        (uint32_t)((wn * 64 + (lane & 7) + ((lane >> 4) & 1) * 8) * QK_WSTR
                   + ((lane >> 3) & 1) * 16);

    float acc[2][8][4];
    #pragma unroll
    for (int i = 0; i < 2; i++)
        #pragma unroll
        for (int j = 0; j < 8; j++)
            #pragma unroll
            for (int q = 0; q < 4; q++) acc[i][j][q] = 0.f;

    #pragma unroll 1
    for (int ch = 0; ch < 4; ch++) {
        if (ch < 3) load_chunk((ch + 1) & 1, (ch + 1) * 64);
        CP_COMMIT();
        CP_WAIT1();
        __syncthreads();
        const uint32_t stb = sb + (ch & 1) * QK_STAGE;
        #pragma unroll
        for (int kk = 0; kk < 4; kk++) {
            uint32_t a[2][4];
            #pragma unroll
            for (int m = 0; m < 2; m++)
                ldsm4t(stb + a_base + kk * 16 * QK_XSTR + m * 32,
                       a[m][0], a[m][1], a[m][2], a[m][3]);
            #pragma unroll
            for (int ng = 0; ng < 4; ng++) {
                uint32_t b0, b1, b2, b3;
                ldsm4(stb + b_base + kk * 32 + ng * 16 * QK_WSTR, b0, b1, b2, b3);
                #pragma unroll
                for (int m = 0; m < 2; m++) {
                    mma16816f(acc[m][2 * ng],     a[m], b0, b1);
                    mma16816f(acc[m][2 * ng + 1], a[m], b2, b3);
                }
            }
        }
        __syncthreads();
    }

    __half* dst = (flavor == 0) ? g_th : g_ph;
    const float* bias = (flavor == 0) ? th_b : ph_b;
    const float scl = (flavor == 0) ? L2E : 1.0f;
    const int m_row = wm * 32 + (lane >> 2);
    const int o_col = wn * 64 + (lane & 3) * 2;
    #pragma unroll
    for (int m = 0; m < 2; m++) {
        #pragma unroll
        for (int n8 = 0; n8 < 8; n8++) {
            float2 bv = *(const float2*)&bias[o_col + n8 * 8];
            int pix = n0 + m_row + m * 16;
            size_t a0 = ((size_t)bb * NPIX + pix) * CIDIM + o_col + n8 * 8;
            *(uint32_t*)&dst[a0] =
                packh2((acc[m][n8][0] + bv.x) * scl, (acc[m][n8][1] + bv.y) * scl);
            size_t a1 = a0 + (size_t)8 * CIDIM;
            *(uint32_t*)&dst[a1] =
                packh2((acc[m][n8][2] + bv.x) * scl, (acc[m][n8][3] + bv.y) * scl);
        }
    }
}

// ================= g projection: bf16 3-pass (precision-critical PV operand) =
#define PJ_XSTR 272
#define PJ_WSTR 144
#define PJ_XH 0
#define PJ_XL 17408
#define PJ_WH 34816
#define PJ_WL 53248
#define PJ_STAGE 71680
#define PROJ_SMEM (2 * PJ_STAGE)

__global__ __launch_bounds__(256, 1) void projg_kernel(const float* __restrict__ g_b)
{
    extern __shared__ char smem[];
    const uint32_t sb = smem_to_u32(smem);
    const int tid = threadIdx.x;
    const int w = tid >> 5, lane = tid & 31;
    const int wm = w & 3, wn = w >> 2;
    const int pt = blockIdx.x;
    const int bb = pt >> 5;
    const int n0 = (pt & 31) * 128;

    const __nv_bfloat16* xh = g_x_h + (size_t)bb * CDIM * NPIX + n0;
    const __nv_bfloat16* xl = g_x_l + (size_t)bb * CDIM * NPIX + n0;
    const __nv_bfloat16* wh = g_wsp_h + 2 * 32768;
    const __nv_bfloat16* wl = g_wsp_l + 2 * 32768;

    auto load_chunk = [&](int s, int k0) {
        uint32_t base = sb + s * PJ_STAGE;
        #pragma unroll
        for (int t = 0; t < 4; t++) {
            int q = tid + t * 256;
            int k = q >> 4, j = q & 15;
            uint32_t d = base + PJ_XH + k * PJ_XSTR + j * 16;
            size_t g = (size_t)(k0 + k) * NPIX + j * 8;
            cp16(d, xh + g);
            cp16(d + (PJ_XL - PJ_XH), xl + g);
        }
        #pragma unroll
        for (int t = 0; t < 4; t++) {
            int q = tid + t * 256;
            int o = q >> 3, j = q & 7;
            uint32_t d = base + PJ_WH + o * PJ_WSTR + j * 16;
            size_t g = (size_t)o * CDIM + k0 + j * 8;
            cp16(d, wh + g);
            cp16(d + (PJ_WL - PJ_WH), wl + g);
        }
    };
    load_chunk(0, 0);
    CP_COMMIT();

    // A = W (non-trans), B = x (trans)
    const uint32_t a_base = PJ_WH +
        (uint32_t)((wm * 32 + (lane & 15)) * PJ_WSTR + (lane >> 4) * 16);
    const uint32_t b_base = PJ_XH +
        (uint32_t)(((lane & 7) + ((lane >> 3) & 1) * 8) * PJ_XSTR
                   + wn * 128 + (lane >> 4) * 16);

    float acc[2][8][4];
    #pragma unroll
    for (int i = 0; i < 2; i++)
        #pragma unroll
        for (int j = 0; j < 8; j++)
            #pragma unroll
            for (int q = 0; q < 4; q++) acc[i][j][q] = 0.f;

    #pragma unroll 1
    for (int ch = 0; ch < 4; ch++) {
        if (ch < 3) load_chunk((ch + 1) & 1, (ch + 1) * 64);
        CP_COMMIT();
        CP_WAIT1();
        __syncthreads();
        const uint32_t stb = sb + (ch & 1) * PJ_STAGE;
        #pragma unroll
        for (int kk = 0; kk < 4; kk++) {
            uint32_t aH[2][4], aL[2][4];
            #pragma unroll
            for (int m = 0; m < 2; m++) {
                uint32_t aa = stb + a_base + kk * 32 + m * 16 * PJ_WSTR;
                ldsm4(aa,                    aH[m][0], aH[m][1], aH[m][2], aH[m][3]);
                ldsm4(aa + (PJ_WL - PJ_WH),  aL[m][0], aL[m][1], aL[m][2], aL[m][3]);
            }
            #pragma unroll
            for (int ng = 0; ng < 4; ng++) {
                uint32_t bh0, bh1, bh2, bh3, bl0, bl1, bl2, bl3;
                uint32_t ba = stb + b_base + kk * 16 * PJ_XSTR + ng * 32;
                ldsm4t(ba,                   bh0, bh1, bh2, bh3);
                ldsm4t(ba + (PJ_XL - PJ_XH), bl0, bl1, bl2, bl3);
                #pragma unroll
                for (int m = 0; m < 2; m++) {
                    mma16816(acc[m][2 * ng],     aH[m], bh0, bh1);
                    mma16816(acc[m][2 * ng + 1], aH[m], bh2, bh3);
                    mma16816(acc[m][2 * ng],     aL[m], bh0, bh1);
                    mma16816(acc[m][2 * ng + 1], aL[m], bh2, bh3);
                    mma16816(acc[m][2 * ng],     aH[m], bl0, bl1);
                    mma16816(acc[m][2 * ng + 1], aH[m], bl2, bl3);
                }
            }
        }
        __syncthreads();
    }

    const int o_row = wm * 32 + (lane >> 2);
    const int p_col = wn * 64 + (lane & 3) * 2;
    #pragma unroll
    for (int m = 0; m < 2; m++) {
        int o = o_row + m * 16;
        float b0 = g_b[o], b1 = g_b[o + 8];
        #pragma unroll
        for (int n8 = 0; n8 < 8; n8++) {
            size_t a0 = ((size_t)bb * CIDIM + o) * NPIX + n0 + p_col + n8 * 8;
            *(uint32_t*)&g_gm_h[a0] =
                packbf2(acc[m][n8][0] + b0, acc[m][n8][1] + b0);
            size_t a1 = a0 + (size_t)8 * NPIX;
            *(uint32_t*)&g_gm_h[a1] =
                packbf2(acc[m][n8][2] + b1, acc[m][n8][3] + b1);
        }
    }
}

// ================= HMMA flash attention (unchanged from R14) =================
#define QSTR 272
#define GSTR 144
#define OFF_Q 0
#define OFF_ST0 34816
#define ST_K 0
#define ST_G 17408
#define STAGE_SZ 35840
#define ATTN_SMEM (OFF_ST0 + 2 * STAGE_SZ)

__global__ __launch_bounds__(256, 2) void attn_kernel()
{
    extern __shared__ char smem[];
    const uint32_t sb = smem_to_u32(smem);
    const int tid = threadIdx.x;
    const int w = tid >> 5, lane = tid & 31;
    const int bb = blockIdx.y;
    const int i0 = blockIdx.x * QT;
    const int ks = blockIdx.z;
    const int jbase = ks * NSPL;

    const __half* qp = g_th + ((size_t)bb * NPIX + i0) * CIDIM;
    const __half* phb = g_ph + (size_t)bb * NPIX * CIDIM;
    const __nv_bfloat16* ghb = g_gm_h + (size_t)bb * CIDIM * NPIX;

    #pragma unroll
    for (int t = 0; t < 8; t++) {
        int q = tid + t * 256;
        int r = q >> 4, c = q & 15;
        cp16(sb + OFF_Q + r * QSTR + c * 16, qp + r * CIDIM + c * 8);
    }

    auto load_stage = [&](int s, int j0) {
        uint32_t base = sb + OFF_ST0 + s * STAGE_SZ;
        #pragma unroll
        for (int t = 0; t < 4; t++) {
            int q = tid + t * 256;
            int j = q >> 4, c = q & 15;
            cp16(base + ST_K + j * QSTR + c * 16,
                 phb + (size_t)(j0 + j) * CIDIM + c * 8);
        }
        #pragma unroll
        for (int t = 0; t < 4; t++) {
            int q = tid + t * 256;
            int c = q >> 3, jc = q & 7;
            cp16(base + ST_G + c * GSTR + jc * 16,
                 ghb + (size_t)c * NPIX + j0 + jc * 8);
        }
    };
    load_stage(0, jbase);
    CP_COMMIT();

    const uint32_t aq_base = sb + OFF_Q +
        (uint32_t)((w * 16 + (lane & 15)) * QSTR + (lane >> 4) * 16);
    const int b_row  = (lane & 7) + ((lane >> 4) & 1) * 8;
    const int b_byte = ((lane >> 3) & 1) * 16;

    float oacc[16][4];
    #pragma unroll
    for (int i = 0; i < 16; i++)
        #pragma unroll
        for (int j = 0; j < 4; j++) oacc[i][j] = 0.f;
    float den0 = 0.f, den1 = 0.f;

    #pragma unroll 1
    for (int jt = 0; jt < NJT_PER; jt++) {
        const int s = jt & 1;
        if (jt + 1 < NJT_PER) load_stage(s ^ 1, jbase + (jt + 1) * JT);
        CP_COMMIT();
        CP_WAIT1();
        __syncthreads();

        const uint32_t stb = sb + OFF_ST0 + s * STAGE_SZ;
        const uint32_t kB = stb + ST_K + (uint32_t)(b_row * QSTR + b_byte);
        const uint32_t gB = stb + ST_G + (uint32_t)(b_row * GSTR + b_byte);

        #pragma unroll
        for (int h = 0; h < 2; h++) {
            float sacc[4][4];
            #pragma unroll
            for (int i = 0; i < 4; i++)
                #pragma unroll
                for (int j = 0; j < 4; j++) sacc[i][j] = 0.f;

            #pragma unroll
            for (int kk = 0; kk < 8; kk++) {
                uint32_t a[4];
                ldsm4(aq_base + kk * 32, a[0], a[1], a[2], a[3]);
                #pragma unroll
                for (int nb = 0; nb < 2; nb++) {
                    uint32_t b0, b1, b2, b3;
                    ldsm4(kB + (uint32_t)((h * 2 + nb) * 16 * QSTR + kk * 32),
                          b0, b1, b2, b3);
                    mma16816f(sacc[2 * nb],     a, b0, b1);
                    mma16816f(sacc[2 * nb + 1], a, b2, b3);
                }
            }

            uint32_t pf[2][4];
            #pragma unroll
            for (int nb = 0; nb < 4; nb++) {
                float e0 = ex2f(sacc[nb][0]);
                float e1 = ex2f(sacc[nb][1]);
                float e2 = ex2f(sacc[nb][2]);
                float e3 = ex2f(sacc[nb][3]);
                den0 += e0 + e1;
                den1 += e2 + e3;
                int kkj = nb >> 1, hf = (nb & 1) * 2;
                pf[kkj][hf]     = packbf2(e0, e1);
                pf[kkj][hf + 1] = packbf2(e2, e3);
            }

            #pragma unroll
            for (int kkj = 0; kkj < 2; kkj++) {
                #pragma unroll
                for (int cb = 0; cb < 8; cb++) {
                    uint32_t b0, b1, b2, b3;
                    ldsm4(gB + (uint32_t)(cb * 16 * GSTR + (h * 2 + kkj) * 32),
                          b0, b1, b2, b3);
                    mma16816(oacc[2 * cb],     pf[kkj], b0, b1);
                    mma16816(oacc[2 * cb + 1], pf[kkj], b2, b3);
                }
            }
        }
        __syncthreads();
    }

    den0 += __shfl_xor_sync(0xFFFFFFFF, den0, 1);
    den0 += __shfl_xor_sync(0xFFFFFFFF, den0, 2);
    den1 += __shfl_xor_sync(0xFFFFFFFF, den1, 1);
    den1 += __shfl_xor_sync(0xFFFFFFFF, den1, 2);

    const int r0 = i0 + w * 16 + (lane >> 2);
    const size_t orow = (size_t)(ks * BATCH + bb) * NPIX + r0;
    float* dst = g_o + orow * CIDIM + (lane & 3) * 2;
    #pragma unroll
    for (int cb = 0; cb < 16; cb++) {
        *(float2*)(dst + cb * 8) = make_float2(oacc[cb][0], oacc[cb][1]);
        *(float2*)(dst + 8 * CIDIM + cb * 8) = make_float2(oacc[cb][2], oacc[cb][3]);
    }
    if ((lane & 3) == 0) {
        g_den[orow]     = den0;
        g_den[orow + 8] = den1;
    }
}

// ================= combine: y = (sum_s O_s)/(sum_s den_s) -> fp16 ===========
#define ROWS_TOT (BATCH * NPIX)
#define F4_PER_SPLIT (ROWS_TOT * CIDIM / 4)

__global__ __launch_bounds__(256) void combine_kernel()
{
    int i = blockIdx.x * 256 + threadIdx.x;
    int row = i >> 5;
    float d = 0.f;
    #pragma unroll
    for (int s = 0; s < KSPLIT; s++) d += g_den[row + s * ROWS_TOT];
    float inv = 1.0f / d;
    const float4* o4 = (const float4*)g_o;
    float v0 = 0.f, v1 = 0.f, v2 = 0.f, v3 = 0.f;
    #pragma unroll
    for (int s = 0; s < KSPLIT; s++) {
        float4 a = o4[i + s * F4_PER_SPLIT];
        v0 += a.x; v1 += a.y; v2 += a.z; v3 += a.w;
    }
    ((uint2*)g_y_f)[i] = make_uint2(packh2(v0 * inv, v1 * inv),
                                    packh2(v2 * inv, v3 * inv));
}

// ================= outproj: out = W_w @ y + b + x (fp16 single-pass) ========
#define OP_STR 272
#define OP_W 0
#define OP_Y 34816
#define OP_SMEM 69632

__global__ __launch_bounds__(256, 1) void outproj_kernel(
    const float* __restrict__ Wb, const float* __restrict__ x,
    float* __restrict__ out)
{
    extern __shared__ char smem[];
    const uint32_t sb = smem_to_u32(smem);
    const int tid = threadIdx.x;
    const int w = tid >> 5, lane = tid & 31;
    const int wm = w & 3, wn = w >> 2;
    const int pt = blockIdx.x;
    const int c0 = blockIdx.y * 128;
    const int bb = pt >> 5;
    const int n0 = (pt & 31) * 128;

    const __half* wwf = g_wf + 2 * 32768;
    const __half* yf = g_y_f + ((size_t)bb * NPIX + n0) * CIDIM;

    #pragma unroll
    for (int t = 0; t < 8; t++) {               // W_w: 128 c-rows x 256B
        int q = tid + t * 256;
        int r = q >> 4, j = q & 15;
        cp16(sb + OP_W + r * OP_STR + j * 16,
             wwf + (size_t)(c0 + r) * CIDIM + j * 8);
    }
    #pragma unroll
    for (int t = 0; t < 8; t++) {               // y: 128 n-rows x 256B
        int q = tid + t * 256;
        int r = q >> 4, j = q & 15;
        cp16(sb + OP_Y + r * OP_STR + j * 16,
             yf + (size_t)r * CIDIM + j * 8);
    }
    CP_COMMIT();
    CP_WAIT0();
    __syncthreads();

    const uint32_t a_base = sb + OP_W +
        (uint32_t)((wm * 32 + (lane & 15)) * OP_STR + (lane >> 4) * 16);
    const uint32_t b_base = sb + OP_Y +
        (uint32_t)((wn * 64 + (lane & 7) + ((lane >> 4) & 1) * 8) * OP_STR
                   + ((lane >> 3) & 1) * 16);

    float acc[2][8][4];
    #pragma unroll
    for (int i = 0; i < 2; i++)
        #pragma unroll
        for (int j = 0; j < 8; j++)
            #pragma unroll
            for (int q = 0; q < 4; q++) acc[i][j][q] = 0.f;

    #pragma unroll
    for (int kk = 0; kk < 8; kk++) {
        uint32_t a[2][4];
        #pragma unroll
        for (int m = 0; m < 2; m++)
            ldsm4(a_base + kk * 32 + m * 16 * OP_STR,
                  a[m][0], a[m][1], a[m][2], a[m][3]);
        #pragma unroll
        for (int ng = 0; ng < 4; ng++) {
            uint32_t b0, b1, b2, b3;
            ldsm4(b_base + kk * 32 + ng * 16 * OP_STR, b0, b1, b2, b3);
            #pragma unroll
            for (int m = 0; m < 2; m++) {
                mma16816f(acc[m][2 * ng],     a[m], b0, b1);
                mma16816f(acc[m][2 * ng + 1], a[m], b2, b3);
            }
        }
    }

    const int c_row = c0 + wm * 32 + (lane >> 2);
    const int p_col = wn * 64 + (lane & 3) * 2;
    #pragma unroll
    for (int m = 0; m < 2; m++) {
        int c = c_row + m * 16;
        float b0 = Wb[c], b1 = Wb[c + 8];
        #pragma unroll
        for (int n8 = 0; n8 < 8; n8++) {
            size_t a0 = ((size_t)bb * CDIM + c) * NPIX + n0 + p_col + n8 * 8;
            float2 xv = *(const float2*)&x[a0];
            *(float2*)&out[a0] = make_float2(acc[m][n8][0] + b0 + xv.x,
                                             acc[m][n8][1] + b0 + xv.y);
            size_t a1 = a0 + (size_t)8 * NPIX;
            float2 xv1 = *(const float2*)&x[a1];
            *(float2*)&out[a1] = make_float2(acc[m][n8][2] + b1 + xv1.x,
                                             acc[m][n8][3] + b1 + xv1.y);
        }
    }
}

extern "C" void kernel_launch(void* const* d_in, const int* in_sizes, int n_in,
                              void* d_out, int out_size) {
    const float* x    = (const float*)d_in[0];
    const float* g_w  = (const float*)d_in[1];
    const float* g_b  = (const float*)d_in[2];
    const float* th_w = (const float*)d_in[3];
    const float* th_b = (const float*)d_in[4];
    const float* ph_w = (const float*)d_in[5];
    const float* ph_b = (const float*)d_in[6];
    const float* W_w  = (const float*)d_in[7];
    const float* W_b  = (const float*)d_in[8];
    float* out = (float*)d_out;

    cudaFuncSetAttribute(projqk_kernel,
                         cudaFuncAttributeMaxDynamicSharedMemorySize, QK_SMEM);
    cudaFuncSetAttribute(projg_kernel,
                         cudaFuncAttributeMaxDynamicSharedMemorySize, PROJ_SMEM);
    cudaFuncSetAttribute(attn_kernel,
                         cudaFuncAttributeMaxDynamicSharedMemorySize, ATTN_SMEM);
    cudaFuncSetAttribute(outproj_kernel,
                         cudaFuncAttributeMaxDynamicSharedMemorySize, OP_SMEM);

    xsplit_kernel<<<BATCH * CDIM * NPIX / 4 / 256, 256>>>(x);
    wsplit_kernel<<<4 * 32768 / 256, 256>>>(th_w, ph_w, g_w, W_w);
    projqk_kernel<<<dim3(BATCH * NPIX / 128, 2), 256, QK_SMEM>>>(th_b, ph_b);
    projg_kernel<<<BATCH * NPIX / 128, 256, PROJ_SMEM>>>(g_b);
    attn_kernel<<<dim3(NPIX / QT, BATCH, KSPLIT), 256, ATTN_SMEM>>>();
    combine_kernel<<<F4_PER_SPLIT / 256, 256>>>();
    outproj_kernel<<<dim3(BATCH * NPIX / 128, CDIM / 128), 256, OP_SMEM>>>(W_b, x, out);
}

// round 17
// speedup vs baseline: 1.8190x; 1.1238x over previous
#include <cuda_runtime.h>
#include <cuda_bf16.h>
#include <cuda_fp16.h>
#include <cstdint>
#include <cstddef>

#define BATCH 8
#define CDIM 256
#define CIDIM 128
#define NPIX 4096
#define QT 128
#define JT 64
#define KSPLIT 8
#define NSPL (NPIX / KSPLIT)
#define NJT_PER (NSPL / JT)
#define L2E 1.4426950408889634f

// ---------------- scratch (__device__ globals; no allocation) ----------------
static __device__ __half        g_x_f [BATCH * CDIM * NPIX];   // fp16 x [B][C][N]
static __device__ __half        g_wf  [4 * 32768];             // th, ph, g, W_w fp16
static __device__ __half        g_th  [BATCH * NPIX * CIDIM];  // fp16, pre-scaled log2e
static __device__ __half        g_ph  [BATCH * NPIX * CIDIM];
static __device__ __nv_bfloat16 g_gm_h[BATCH * CIDIM * NPIX];  // bf16 (PV operand)
static __device__ __half        g_y_f [BATCH * NPIX * CIDIM];  // fp16 y
static __device__ __half        g_op  [KSPLIT * BATCH * NPIX * CIDIM]; // fp16 normalized partials
static __device__ float         g_den [KSPLIT * BATCH * NPIX];

// ---------------- PTX helpers ----------------
__device__ __forceinline__ uint32_t smem_to_u32(const void* p) {
    uint32_t a;
    asm("{ .reg .u64 t; cvta.to.shared.u64 t, %1; cvt.u32.u64 %0, t; }"
        : "=r"(a) : "l"(p));
    return a;
}
__device__ __forceinline__ void cp16(uint32_t dst, const void* src) {
    asm volatile("cp.async.cg.shared.global [%0], [%1], 16;" :: "r"(dst), "l"(src) : "memory");
}
#define CP_COMMIT() asm volatile("cp.async.commit_group;" ::: "memory")
#define CP_WAIT0()  asm volatile("cp.async.wait_group 0;" ::: "memory")
#define CP_WAIT1()  asm volatile("cp.async.wait_group 1;" ::: "memory")

__device__ __forceinline__ void ldsm4(uint32_t a, uint32_t& r0, uint32_t& r1,
                                      uint32_t& r2, uint32_t& r3) {
    asm volatile("ldmatrix.sync.aligned.m8n8.x4.shared.b16 {%0,%1,%2,%3}, [%4];"
                 : "=r"(r0), "=r"(r1), "=r"(r2), "=r"(r3) : "r"(a));
}
__device__ __forceinline__ void ldsm4t(uint32_t a, uint32_t& r0, uint32_t& r1,
                                       uint32_t& r2, uint32_t& r3) {
    asm volatile("ldmatrix.sync.aligned.m8n8.x4.trans.shared.b16 {%0,%1,%2,%3}, [%4];"
                 : "=r"(r0), "=r"(r1), "=r"(r2), "=r"(r3) : "r"(a));
}
__device__ __forceinline__ void mma16816(float* d, const uint32_t* a,
                                         uint32_t b0, uint32_t b1) {
    asm volatile("mma.sync.aligned.m16n8k16.row.col.f32.bf16.bf16.f32 "
                 "{%0,%1,%2,%3}, {%4,%5,%6,%7}, {%8,%9}, {%0,%1,%2,%3};"
                 : "+f"(d[0]), "+f"(d[1]), "+f"(d[2]), "+f"(d[3])
                 : "r"(a[0]), "r"(a[1]), "r"(a[2]), "r"(a[3]), "r"(b0), "r"(b1));
}
__device__ __forceinline__ void mma16816f(float* d, const uint32_t* a,
                                          uint32_t b0, uint32_t b1) {
    asm volatile("mma.sync.aligned.m16n8k16.row.col.f32.f16.f16.f32 "
                 "{%0,%1,%2,%3}, {%4,%5,%6,%7}, {%8,%9}, {%0,%1,%2,%3};"
                 : "+f"(d[0]), "+f"(d[1]), "+f"(d[2]), "+f"(d[3])
                 : "r"(a[0]), "r"(a[1]), "r"(a[2]), "r"(a[3]), "r"(b0), "r"(b1));
}
__device__ __forceinline__ uint32_t packbf2(float lo, float hi) {
    uint32_t r;
    asm("cvt.rn.satfinite.bf16x2.f32 %0, %1, %2;" : "=r"(r) : "f"(hi), "f"(lo));
    return r;
}
__device__ __forceinline__ uint32_t packh2(float lo, float hi) {
    uint32_t r;
    asm("cvt.rn.f16x2.f32 %0, %1, %2;" : "=r"(r) : "f"(hi), "f"(lo));
    return r;
}
__device__ __forceinline__ float ex2f(float x) {
    float r;
    asm("ex2.approx.f32 %0, %1;" : "=f"(r) : "f"(x));
    return r;
}

// ================= convert kernels =================
__global__ __launch_bounds__(256) void xsplit_kernel(const float* __restrict__ x) {
    int i = blockIdx.x * 256 + threadIdx.x;
    float4 v = ((const float4*)x)[i];
    ((uint2*)g_x_f)[i] = make_uint2(packh2(v.x, v.y), packh2(v.z, v.w));
}
__global__ __launch_bounds__(256) void wsplit_kernel(
    const float* __restrict__ thw, const float* __restrict__ phw,
    const float* __restrict__ gw,  const float* __restrict__ Ww) {
    int idx = blockIdx.x * 256 + threadIdx.x;
    int seg = idx >> 15, loc = idx & 32767;
    const float* src = (seg == 0) ? thw : (seg == 1) ? phw : (seg == 2) ? gw : Ww;
    g_wf[idx] = __float2half(src[loc]);
}

// ================= theta/phi projection: fp16 single-pass ===================
#define QK_XSTR 272
#define QK_WSTR 144
#define QK_X 0
#define QK_W 17408
#define QK_STAGE 35840
#define QK_SMEM (2 * QK_STAGE)

__global__ __launch_bounds__(256, 2) void projqk_kernel(
    const float* __restrict__ th_b, const float* __restrict__ ph_b)
{
    extern __shared__ char smem[];
    const uint32_t sb = smem_to_u32(smem);
    const int tid = threadIdx.x;
    const int w = tid >> 5, lane = tid & 31;
    const int wm = w & 3, wn = w >> 2;
    const int flavor = blockIdx.y;
    const int pt = blockIdx.x;
    const int bb = pt >> 5;
    const int n0 = (pt & 31) * 128;

    const __half* xf = g_x_f + (size_t)bb * CDIM * NPIX + n0;
    const __half* wf = g_wf + flavor * 32768;

    auto load_chunk = [&](int s, int k0) {
        uint32_t base = sb + s * QK_STAGE;
        #pragma unroll
        for (int t = 0; t < 4; t++) {
            int q = tid + t * 256;
            int k = q >> 4, j = q & 15;
            cp16(base + QK_X + k * QK_XSTR + j * 16,
                 xf + (size_t)(k0 + k) * NPIX + j * 8);
        }
        #pragma unroll
        for (int t = 0; t < 4; t++) {
            int q = tid + t * 256;
            int o = q >> 3, j = q & 7;
            cp16(base + QK_W + o * QK_WSTR + j * 16,
                 wf + (size_t)o * CDIM + k0 + j * 8);
        }
    };
    load_chunk(0, 0);
    CP_COMMIT();

    const uint32_t a_base = QK_X +
        (uint32_t)(((lane & 7) + ((lane >> 4) & 1) * 8) * QK_XSTR
                   + wm * 64 + ((lane >> 3) & 1) * 16);
    const uint32_t b_base = QK_W +
        (uint32_t)((wn * 64 + (lane & 7) + ((lane >> 4) & 1) * 8) * QK_WSTR
                   + ((lane >> 3) & 1) * 16);

    float acc[2][8][4];
    #pragma unroll
    for (int i = 0; i < 2; i++)
        #pragma unroll
        for (int j = 0; j < 8; j++)
            #pragma unroll
            for (int q = 0; q < 4; q++) acc[i][j][q] = 0.f;

    #pragma unroll 1
    for (int ch = 0; ch < 4; ch++) {
        if (ch < 3) load_chunk((ch + 1) & 1, (ch + 1) * 64);
        CP_COMMIT();
        CP_WAIT1();
        __syncthreads();
        const uint32_t stb = sb + (ch & 1) * QK_STAGE;
        #pragma unroll
        for (int kk = 0; kk < 4; kk++) {
            uint32_t a[2][4];
            #pragma unroll
            for (int m = 0; m < 2; m++)
                ldsm4t(stb + a_base + kk * 16 * QK_XSTR + m * 32,
                       a[m][0], a[m][1], a[m][2], a[m][3]);
            #pragma unroll
            for (int ng = 0; ng < 4; ng++) {
                uint32_t b0, b1, b2, b3;
                ldsm4(stb + b_base + kk * 32 + ng * 16 * QK_WSTR, b0, b1, b2, b3);
                #pragma unroll
                for (int m = 0; m < 2; m++) {
                    mma16816f(acc[m][2 * ng],     a[m], b0, b1);
                    mma16816f(acc[m][2 * ng + 1], a[m], b2, b3);
                }
            }
        }
        __syncthreads();
    }

    __half* dst = (flavor == 0) ? g_th : g_ph;
    const float* bias = (flavor == 0) ? th_b : ph_b;
    const float scl = (flavor == 0) ? L2E : 1.0f;
    const int m_row = wm * 32 + (lane >> 2);
    const int o_col = wn * 64 + (lane & 3) * 2;
    #pragma unroll
    for (int m = 0; m < 2; m++) {
        #pragma unroll
        for (int n8 = 0; n8 < 8; n8++) {
            float2 bv = *(const float2*)&bias[o_col + n8 * 8];
            int pix = n0 + m_row + m * 16;
            size_t a0 = ((size_t)bb * NPIX + pix) * CIDIM + o_col + n8 * 8;
            *(uint32_t*)&dst[a0] =
                packh2((acc[m][n8][0] + bv.x) * scl, (acc[m][n8][1] + bv.y) * scl);
            size_t a1 = a0 + (size_t)8 * CIDIM;
            *(uint32_t*)&dst[a1] =
                packh2((acc[m][n8][2] + bv.x) * scl, (acc[m][n8][3] + bv.y) * scl);
        }
    }
}

// ================= g projection: fp16 single-pass -> bf16 out ===============
// out[ci][pix] ; A = W fp16 (non-trans), B = x fp16 (trans)
__global__ __launch_bounds__(256, 2) void projg_kernel(const float* __restrict__ g_b)
{
    extern __shared__ char smem[];
    const uint32_t sb = smem_to_u32(smem);
    const int tid = threadIdx.x;
    const int w = tid >> 5, lane = tid & 31;
    const int wm = w & 3, wn = w >> 2;
    const int pt = blockIdx.x;
    const int bb = pt >> 5;
    const int n0 = (pt & 31) * 128;

    const __half* xf = g_x_f + (size_t)bb * CDIM * NPIX + n0;
    const __half* wf = g_wf + 2 * 32768;

    auto load_chunk = [&](int s, int k0) {
        uint32_t base = sb + s * QK_STAGE;
        #pragma unroll
        for (int t = 0; t < 4; t++) {
            int q = tid + t * 256;
            int k = q >> 4, j = q & 15;
            cp16(base + QK_X + k * QK_XSTR + j * 16,
                 xf + (size_t)(k0 + k) * NPIX + j * 8);
        }
        #pragma unroll
        for (int t = 0; t < 4; t++) {
            int q = tid + t * 256;
            int o = q >> 3, j = q & 7;
            cp16(base + QK_W + o * QK_WSTR + j * 16,
                 wf + (size_t)o * CDIM + k0 + j * 8);
        }
    };
    load_chunk(0, 0);
    CP_COMMIT();

    // A = W (non-trans): 32 o-rows per warp ; B = x (trans): 128 pix cols
    const uint32_t a_base = QK_W +
        (uint32_t)((wm * 32 + (lane & 15)) * QK_WSTR + (lane >> 4) * 16);
    const uint32_t b_base = QK_X +
        (uint32_t)(((lane & 7) + ((lane >> 3) & 1) * 8) * QK_XSTR
                   + wn * 128 + (lane >> 4) * 16);

    float acc[2][8][4];
    #pragma unroll
    for (int i = 0; i < 2; i++)
        #pragma unroll
        for (int j = 0; j < 8; j++)
            #pragma unroll
            for (int q = 0; q < 4; q++) acc[i][j][q] = 0.f;

    #pragma unroll 1
    for (int ch = 0; ch < 4; ch++) {
        if (ch < 3) load_chunk((ch + 1) & 1, (ch + 1) * 64);
        CP_COMMIT();
        CP_WAIT1();
        __syncthreads();
        const uint32_t stb = sb + (ch & 1) * QK_STAGE;
        #pragma unroll
        for (int kk = 0; kk < 4; kk++) {
            uint32_t a[2][4];
            #pragma unroll
            for (int m = 0; m < 2; m++)
                ldsm4(stb + a_base + kk * 32 + m * 16 * QK_WSTR,
                      a[m][0], a[m][1], a[m][2], a[m][3]);
            #pragma unroll
            for (int ng = 0; ng < 4; ng++) {
                uint32_t b0, b1, b2, b3;
                ldsm4t(stb + b_base + kk * 16 * QK_XSTR + ng * 32, b0, b1, b2, b3);
                #pragma unroll
                for (int m = 0; m < 2; m++) {
                    mma16816f(acc[m][2 * ng],     a[m], b0, b1);
                    mma16816f(acc[m][2 * ng + 1], a[m], b2, b3);
                }
            }
        }
        __syncthreads();
    }

    const int o_row = wm * 32 + (lane >> 2);
    const int p_col = wn * 64 + (lane & 3) * 2;
    #pragma unroll
    for (int m = 0; m < 2; m++) {
        int o = o_row + m * 16;
        float b0 = g_b[o], b1 = g_b[o + 8];
        #pragma unroll
        for (int n8 = 0; n8 < 8; n8++) {
            size_t a0 = ((size_t)bb * CIDIM + o) * NPIX + n0 + p_col + n8 * 8;
            *(uint32_t*)&g_gm_h[a0] =
                packbf2(acc[m][n8][0] + b0, acc[m][n8][1] + b0);
            size_t a1 = a0 + (size_t)8 * NPIX;
            *(uint32_t*)&g_gm_h[a1] =
                packbf2(acc[m][n8][2] + b1, acc[m][n8][3] + b1);
        }
    }
}

// ================= HMMA flash attention (fp16 S, 2 CTAs/SM, fp16 partials) ==
#define QSTR 272
#define GSTR 144
#define OFF_Q 0
#define OFF_ST0 34816
#define ST_K 0
#define ST_G 17408
#define STAGE_SZ 35840
#define ATTN_SMEM (OFF_ST0 + 2 * STAGE_SZ)

__global__ __launch_bounds__(256, 2) void attn_kernel()
{
    extern __shared__ char smem[];
    const uint32_t sb = smem_to_u32(smem);
    const int tid = threadIdx.x;
    const int w = tid >> 5, lane = tid & 31;
    const int bb = blockIdx.y;
    const int i0 = blockIdx.x * QT;
    const int ks = blockIdx.z;
    const int jbase = ks * NSPL;

    const __half* qp = g_th + ((size_t)bb * NPIX + i0) * CIDIM;
    const __half* phb = g_ph + (size_t)bb * NPIX * CIDIM;
    const __nv_bfloat16* ghb = g_gm_h + (size_t)bb * CIDIM * NPIX;

    #pragma unroll
    for (int t = 0; t < 8; t++) {
        int q = tid + t * 256;
        int r = q >> 4, c = q & 15;
        cp16(sb + OFF_Q + r * QSTR + c * 16, qp + r * CIDIM + c * 8);
    }

    auto load_stage = [&](int s, int j0) {
        uint32_t base = sb + OFF_ST0 + s * STAGE_SZ;
        #pragma unroll
        for (int t = 0; t < 4; t++) {
            int q = tid + t * 256;
            int j = q >> 4, c = q & 15;
            cp16(base + ST_K + j * QSTR + c * 16,
                 phb + (size_t)(j0 + j) * CIDIM + c * 8);
        }
        #pragma unroll
        for (int t = 0; t < 4; t++) {
            int q = tid + t * 256;
            int c = q >> 3, jc = q & 7;
            cp16(base + ST_G + c * GSTR + jc * 16,
                 ghb + (size_t)c * NPIX + j0 + jc * 8);
        }
    };
    load_stage(0, jbase);
    CP_COMMIT();

    const uint32_t aq_base = sb + OFF_Q +
        (uint32_t)((w * 16 + (lane & 15)) * QSTR + (lane >> 4) * 16);
    const int b_row  = (lane & 7) + ((lane >> 4) & 1) * 8;
    const int b_byte = ((lane >> 3) & 1) * 16;

    float oacc[16][4];
    #pragma unroll
    for (int i = 0; i < 16; i++)
        #pragma unroll
        for (int j = 0; j < 4; j++) oacc[i][j] = 0.f;
    float den0 = 0.f, den1 = 0.f;

    #pragma unroll 1
    for (int jt = 0; jt < NJT_PER; jt++) {
        const int s = jt & 1;
        if (jt + 1 < NJT_PER) load_stage(s ^ 1, jbase + (jt + 1) * JT);
        CP_COMMIT();
        CP_WAIT1();
        __syncthreads();

        const uint32_t stb = sb + OFF_ST0 + s * STAGE_SZ;
        const uint32_t kB = stb + ST_K + (uint32_t)(b_row * QSTR + b_byte);
        const uint32_t gB = stb + ST_G + (uint32_t)(b_row * GSTR + b_byte);

        #pragma unroll
        for (int h = 0; h < 2; h++) {
            float sacc[4][4];
            #pragma unroll
            for (int i = 0; i < 4; i++)
                #pragma unroll
                for (int j = 0; j < 4; j++) sacc[i][j] = 0.f;

            #pragma unroll
            for (int kk = 0; kk < 8; kk++) {
                uint32_t a[4];
                ldsm4(aq_base + kk * 32, a[0], a[1], a[2], a[3]);
                #pragma unroll
                for (int nb = 0; nb < 2; nb++) {
                    uint32_t b0, b1, b2, b3;
                    ldsm4(kB + (uint32_t)((h * 2 + nb) * 16 * QSTR + kk * 32),
                          b0, b1, b2, b3);
                    mma16816f(sacc[2 * nb],     a, b0, b1);
                    mma16816f(sacc[2 * nb + 1], a, b2, b3);
                }
            }

            uint32_t pf[2][4];
            #pragma unroll
            for (int nb = 0; nb < 4; nb++) {
                float e0 = ex2f(sacc[nb][0]);
                float e1 = ex2f(sacc[nb][1]);
                float e2 = ex2f(sacc[nb][2]);
                float e3 = ex2f(sacc[nb][3]);
                den0 += e0 + e1;
                den1 += e2 + e3;
                int kkj = nb >> 1, hf = (nb & 1) * 2;
                pf[kkj][hf]     = packbf2(e0, e1);
                pf[kkj][hf + 1] = packbf2(e2, e3);
            }

            #pragma unroll
            for (int kkj = 0; kkj < 2; kkj++) {
                #pragma unroll
                for (int cb = 0; cb < 8; cb++) {
                    uint32_t b0, b1, b2, b3;
                    ldsm4(gB + (uint32_t)(cb * 16 * GSTR + (h * 2 + kkj) * 32),
                          b0, b1, b2, b3);
                    mma16816(oacc[2 * cb],     pf[kkj], b0, b1);
                    mma16816(oacc[2 * cb + 1], pf[kkj], b2, b3);
                }
            }
        }
        __syncthreads();
    }

    den0 += __shfl_xor_sync(0xFFFFFFFF, den0, 1);
    den0 += __shfl_xor_sync(0xFFFFFFFF, den0, 2);
    den1 += __shfl_xor_sync(0xFFFFFFFF, den1, 1);
    den1 += __shfl_xor_sync(0xFFFFFFFF, den1, 2);
    const float inv0 = 1.0f / den0;
    const float inv1 = 1.0f / den1;

    // normalized fp16 partials (bounded by |g| -> fp16-safe)
    const int r0 = i0 + w * 16 + (lane >> 2);
    const size_t orow = (size_t)(ks * BATCH + bb) * NPIX + r0;
    __half* dst = g_op + orow * CIDIM + (lane & 3) * 2;
    #pragma unroll
    for (int cb = 0; cb < 16; cb++) {
        *(uint32_t*)&dst[cb * 8] =
            packh2(oacc[cb][0] * inv0, oacc[cb][1] * inv0);
        *(uint32_t*)&dst[8 * CIDIM + cb * 8] =
            packh2(oacc[cb][2] * inv1, oacc[cb][3] * inv1);
    }
    if ((lane & 3) == 0) {
        g_den[orow]     = den0;
        g_den[orow + 8] = den1;
    }
}

// ================= combine: y = sum_s (den_s/sum den) * yhat_s ==============
#define ROWS_TOT (BATCH * NPIX)
#define H4_PER_SPLIT (ROWS_TOT * CIDIM / 4)    // uint2 units (4 halves)

__global__ __launch_bounds__(256) void combine_kernel()
{
    int i = blockIdx.x * 256 + threadIdx.x;
    int row = i >> 5;
    float dsum = 0.f;
    float ds[KSPLIT];
    #pragma unroll
    for (int s = 0; s < KSPLIT; s++) { ds[s] = g_den[row + s * ROWS_TOT]; dsum += ds[s]; }
    float invd = 1.0f / dsum;
    float v0 = 0.f, v1 = 0.f, v2 = 0.f, v3 = 0.f;
    const uint2* op = (const uint2*)g_op;
    #pragma unroll
    for (int s = 0; s < KSPLIT; s++) {
        float ws = ds[s] * invd;
        uint2 u = op[i + s * H4_PER_SPLIT];
        __half2 h01 = *(__half2*)&u.x;
        __half2 h23 = *(__half2*)&u.y;
        float2 f01 = __half22float2(h01);
        float2 f23 = __half22float2(h23);
        v0 += ws * f01.x; v1 += ws * f01.y;
        v2 += ws * f23.x; v3 += ws * f23.y;
    }
    ((uint2*)g_y_f)[i] = make_uint2(packh2(v0, v1), packh2(v2, v3));
}

// ================= outproj: out = W_w @ y + b + x (fp16 single-pass) ========
#define OP_STR 272
#define OP_W 0
#define OP_Y 34816
#define OP_SMEM 69632

__global__ __launch_bounds__(256, 2) void outproj_kernel(
    const float* __restrict__ Wb, const float* __restrict__ x,
    float* __restrict__ out)
{
    extern __shared__ char smem[];
    const uint32_t sb = smem_to_u32(smem);
    const int tid = threadIdx.x;
    const int w = tid >> 5, lane = tid & 31;
    const int wm = w & 3, wn = w >> 2;
    const int pt = blockIdx.x;
    const int c0 = blockIdx.y * 128;
    const int bb = pt >> 5;
    const int n0 = (pt & 31) * 128;

    const __half* wwf = g_wf + 3 * 32768;
    const __half* yf = g_y_f + ((size_t)bb * NPIX + n0) * CIDIM;

    #pragma unroll
    for (int t = 0; t < 8; t++) {
        int q = tid + t * 256;
        int r = q >> 4, j = q & 15;
        cp16(sb + OP_W + r * OP_STR + j * 16,
             wwf + (size_t)(c0 + r) * CIDIM + j * 8);
    }
    #pragma unroll
    for (int t = 0; t < 8; t++) {
        int q = tid + t * 256;
        int r = q >> 4, j = q & 15;
        cp16(sb + OP_Y + r * OP_STR + j * 16,
             yf + (size_t)r * CIDIM + j * 8);
    }
    CP_COMMIT();
    CP_WAIT0();
    __syncthreads();

    const uint32_t a_base = sb + OP_W +
        (uint32_t)((wm * 32 + (lane & 15)) * OP_STR + (lane >> 4) * 16);
    const uint32_t b_base = sb + OP_Y +
        (uint32_t)((wn * 64 + (lane & 7) + ((lane >> 4) & 1) * 8) * OP_STR
                   + ((lane >> 3) & 1) * 16);

    float acc[2][8][4];
    #pragma unroll
    for (int i = 0; i < 2; i++)
        #pragma unroll
        for (int j = 0; j < 8; j++)
            #pragma unroll
            for (int q = 0; q < 4; q++) acc[i][j][q] = 0.f;

    #pragma unroll
    for (int kk = 0; kk < 8; kk++) {
        uint32_t a[2][4];
        #pragma unroll
        for (int m = 0; m < 2; m++)
            ldsm4(a_base + kk * 32 + m * 16 * OP_STR,
                  a[m][0], a[m][1], a[m][2], a[m][3]);
        #pragma unroll
        for (int ng = 0; ng < 4; ng++) {
            uint32_t b0, b1, b2, b3;
            ldsm4(b_base + kk * 32 + ng * 16 * OP_STR, b0, b1, b2, b3);
            #pragma unroll
            for (int m = 0; m < 2; m++) {
                mma16816f(acc[m][2 * ng],     a[m], b0, b1);
                mma16816f(acc[m][2 * ng + 1], a[m], b2, b3);
            }
        }
    }

    const int c_row = c0 + wm * 32 + (lane >> 2);
    const int p_col = wn * 64 + (lane & 3) * 2;
    #pragma unroll
    for (int m = 0; m < 2; m++) {
        int c = c_row + m * 16;
        float b0 = Wb[c], b1 = Wb[c + 8];
        #pragma unroll
        for (int n8 = 0; n8 < 8; n8++) {
            size_t a0 = ((size_t)bb * CDIM + c) * NPIX + n0 + p_col + n8 * 8;
            float2 xv = *(const float2*)&x[a0];
            *(float2*)&out[a0] = make_float2(acc[m][n8][0] + b0 + xv.x,
                                             acc[m][n8][1] + b0 + xv.y);
            size_t a1 = a0 + (size_t)8 * NPIX;
            float2 xv1 = *(const float2*)&x[a1];
            *(float2*)&out[a1] = make_float2(acc[m][n8][2] + b1 + xv1.x,
                                             acc[m][n8][3] + b1 + xv1.y);
        }
    }
}

extern "C" void kernel_launch(void* const* d_in, const int* in_sizes, int n_in,
                              void* d_out, int out_size) {
    const float* x    = (const float*)d_in[0];
    const float* g_w  = (const float*)d_in[1];
    const float* g_b  = (const float*)d_in[2];
    const float* th_w = (const float*)d_in[3];
    const float* th_b = (const float*)d_in[4];
    const float* ph_w = (const float*)d_in[5];
    const float* ph_b = (const float*)d_in[6];
    const float* W_w  = (const float*)d_in[7];
    const float* W_b  = (const float*)d_in[8];
    float* out = (float*)d_out;

    cudaFuncSetAttribute(projqk_kernel,
                         cudaFuncAttributeMaxDynamicSharedMemorySize, QK_SMEM);
    cudaFuncSetAttribute(projg_kernel,
                         cudaFuncAttributeMaxDynamicSharedMemorySize, QK_SMEM);
    cudaFuncSetAttribute(attn_kernel,
                         cudaFuncAttributeMaxDynamicSharedMemorySize, ATTN_SMEM);
    cudaFuncSetAttribute(outproj_kernel,
                         cudaFuncAttributeMaxDynamicSharedMemorySize, OP_SMEM);

    xsplit_kernel<<<BATCH * CDIM * NPIX / 4 / 256, 256>>>(x);
    wsplit_kernel<<<4 * 32768 / 256, 256>>>(th_w, ph_w, g_w, W_w);
    projqk_kernel<<<dim3(BATCH * NPIX / 128, 2), 256, QK_SMEM>>>(th_b, ph_b);
    projg_kernel<<<BATCH * NPIX / 128, 256, QK_SMEM>>>(g_b);
    attn_kernel<<<dim3(NPIX / QT, BATCH, KSPLIT), 256, ATTN_SMEM>>>();
    combine_kernel<<<H4_PER_SPLIT / 256, 256>>>();
    outproj_kernel<<<dim3(BATCH * NPIX / 128, CDIM / 128), 256, OP_SMEM>>>(W_b, x, out);
}